// round 5
// baseline (speedup 1.0000x reference)
#include <cuda_runtime.h>
#include <math.h>

// ---------------- problem constants ----------------
#define BB 4
#define HH 256
#define WW 256
#define HWSZ (HH*WW)

typedef unsigned long long ull;

// ---------------- scratch buffers ----------------
__device__ float g_cat [(size_t)BB*128*HWSZ];  // f1 (ch0..63) | f2 (ch64..127)
__device__ float g_x128[(size_t)BB*128*HWSZ];  // fc1 output
__device__ float g_corr[(size_t)BB*128*HWSZ];  // feat (0..63) | lc (64..112) | zero pad
__device__ float g_f1s [(size_t)BB*64*HWSZ];   // blurred f1
__device__ float g_tmp [(size_t)BB*64*HWSZ];   // blur horizontal pass scratch
__device__ float g_x64 [(size_t)BB*64*HWSZ];
__device__ float g_x32 [(size_t)BB*32*HWSZ];
__device__ float g_x16 [(size_t)BB*16*HWSZ];
__device__ float g_head[(size_t)BB*2*HWSZ];
__device__ float g_lcsum[BB];
// prepped (reordered + tf32-rounded, ci-padded) weights
__device__ float g_wp[36864 + 147456 + 73728 + 73728 + 18432 + 4608];

// gaussian 1d kernel (sigma=1.5, size 7)
__constant__ float GK[7] = {0.03663285f, 0.11128102f, 0.21674443f, 0.27068263f,
                            0.21674443f, 0.11128102f, 0.03663285f};

// ---------------- helpers ----------------
__device__ __forceinline__ unsigned f2tf(float f) {
    unsigned r; asm("cvt.rna.tf32.f32 %0, %1;" : "=r"(r) : "f"(f)); return r;
}
__device__ __forceinline__ void mma8(float* d, const unsigned* a, const unsigned* b) {
    asm volatile("mma.sync.aligned.m16n8k8.row.col.f32.tf32.tf32.f32 "
        "{%0,%1,%2,%3}, {%4,%5,%6,%7}, {%8,%9}, {%0,%1,%2,%3};\n"
        : "+f"(d[0]), "+f"(d[1]), "+f"(d[2]), "+f"(d[3])
        : "r"(a[0]), "r"(a[1]), "r"(a[2]), "r"(a[3]), "r"(b[0]), "r"(b[1]));
}
__device__ __forceinline__ ull pk2(float lo, float hi) {
    ull r; asm("mov.b64 %0, {%1, %2};" : "=l"(r) : "f"(lo), "f"(hi)); return r;
}
__device__ __forceinline__ void fma2(ull& d, ull a, ull b) {
    asm("fma.rn.f32x2 %0, %1, %2, %0;" : "+l"(d) : "l"(a), "l"(b));
}
__device__ __forceinline__ ull add2(ull a, ull b) {
    ull r; asm("add.rn.f32x2 %0, %1, %2;" : "=l"(r) : "l"(a), "l"(b)); return r;
}

// ---------------- weight prep: OIHW -> [k9][CINP][COUT], tf32-rounded ------
__global__ void prep_w_kernel(const float* __restrict__ w, float* __restrict__ wp,
                              int COUT, int CIN, int CINP)
{
    int idx = blockIdx.x*256 + threadIdx.x;
    int total = 9*CINP*COUT;
    if (idx >= total) return;
    int co = idx % COUT;
    int t  = idx / COUT;
    int ci = t % CINP;
    int k9 = t / CINP;
    float v = (ci < CIN) ? w[((size_t)(co*CIN + ci))*9 + k9] : 0.f;
    wp[idx] = __uint_as_float(f2tf(v));
}

// ---------------- tf32 tensor-core 3x3 conv, RY=2 rows per CTA -------------
// CTA = 512 threads (16 warps = 2 row-groups x 8 m/n-warps).
// Each CTA: 128-px strip x 2 output rows x COUT channels.
#define KC 8
#define PWD 136   // padded smem row width (136 % 32 == 8 -> conflict-free)

template<int COUT, int CIN, int DIL>
__global__ __launch_bounds__(512)
void conv_mma(const float* __restrict__ in, int CinS, int cinOff,
              const float* __restrict__ wp, const float* __restrict__ bias,
              float* __restrict__ out, int CoutS, int coutOff)
{
    constexpr int WM = (COUT >= 32) ? 32 : COUT;
    constexpr int NMW = COUT / WM;
    constexpr int NNW = 8 / NMW;
    constexpr int WN  = 128 / NNW;
    constexpr int MTILES = WM / 16;
    constexpr int NTILES = WN / 8;
    constexpr int CP  = COUT + 8;
    constexpr int PWU = 128 + 2*DIL;
    constexpr int NROWS = 2 + 2*DIL;

    extern __shared__ __align__(16) unsigned smem_u[];
    unsigned* s_in = smem_u;                      // [NROWS][KC][PWD]
    unsigned* s_w  = smem_u + NROWS*KC*PWD;       // [9][KC][CP]

    const int tid = threadIdx.x;
    const int x0  = blockIdx.x * 128;
    const int y0  = blockIdx.y * 2;
    const int bz  = blockIdx.z;
    const int wid = tid >> 5, lane = tid & 31;
    const int g = lane >> 2, c = lane & 3;
    const int wy = wid >> 3;           // row group 0/1
    const int w8 = wid & 7;
    const int wm = w8 % NMW, wn = w8 / NMW;

    float acc[MTILES][NTILES][4];
#pragma unroll
    for (int mt=0; mt<MTILES; mt++)
#pragma unroll
        for (int nt=0; nt<NTILES; nt++)
#pragma unroll
            for (int r=0; r<4; r++) acc[mt][nt][r] = 0.f;

#pragma unroll 1
    for (int ci0 = 0; ci0 < CIN; ci0 += KC) {
        __syncthreads();
        // fill input strip (NROWS rows x KC ch x PWU px), zero pad at borders
        {
            constexpr int FILLN = NROWS*KC*PWU;
            for (int idx = tid; idx < FILLN; idx += 512) {
                int px  = idx % PWU;
                int t   = idx / PWU;
                int ci  = t % KC;
                int row = t / KC;
                int gy = y0 - DIL + row;
                int gx = x0 - DIL + px;
                float v = 0.f;
                if (gy >= 0 && gy < HH && gx >= 0 && gx < WW)
                    v = in[((size_t)(bz*CinS + cinOff + ci0 + ci))*HWSZ + (size_t)gy*WW + gx];
                s_in[(row*KC + ci)*PWD + px] = f2tf(v);
            }
        }
        // fill weights [9][KC][CP]
        {
            constexpr int NW4 = 9*KC*(COUT/4);
            const float4* wp4base = (const float4*)wp;
            for (int idx = tid; idx < NW4; idx += 512) {
                int co4 = idx % (COUT/4);
                int t   = idx / (COUT/4);
                int ci  = t % KC;
                int k9  = t / KC;
                float4 v = wp4base[((size_t)(k9*CIN + ci0 + ci))*(COUT/4) + co4];
                *(float4*)((float*)s_w + (k9*KC + ci)*CP + co4*4) = v;
            }
        }
        __syncthreads();

#pragma unroll
        for (int ky=0; ky<3; ky++) {
#pragma unroll
            for (int kx=0; kx<3; kx++) {
                unsigned a[MTILES][4];
#pragma unroll
                for (int mt=0; mt<MTILES; mt++) {
                    const unsigned* wb = s_w + ((ky*3+kx)*KC + c)*CP + wm*WM + mt*16 + g;
                    a[mt][0] = wb[0];
                    a[mt][1] = wb[8];
                    a[mt][2] = wb[4*CP];
                    a[mt][3] = wb[4*CP + 8];
                }
                const int srow = wy + ky*DIL;
                const int xoff = kx*DIL + wn*WN;
#pragma unroll
                for (int nt=0; nt<NTILES; nt++) {
                    const unsigned* bb = s_in + (srow*KC + c)*PWD + xoff + nt*8 + g;
                    unsigned bv[2];
                    bv[0] = bb[0];
                    bv[1] = bb[4*PWD];
#pragma unroll
                    for (int mt=0; mt<MTILES; mt++)
                        mma8(acc[mt][nt], a[mt], bv);
                }
            }
        }
    }

    // epilogue -> NCHW
    const int y = y0 + wy;
#pragma unroll
    for (int mt=0; mt<MTILES; mt++) {
        const int co0 = wm*WM + mt*16 + g;
        const float b0v = bias ? bias[co0]     : 0.f;
        const float b1v = bias ? bias[co0 + 8] : 0.f;
        float* o0 = out + ((size_t)(bz*CoutS + coutOff + co0))*HWSZ + (size_t)y*WW + x0 + wn*WN;
        float* o1 = o0 + (size_t)8*HWSZ;
#pragma unroll
        for (int nt=0; nt<NTILES; nt++) {
            const int px = nt*8 + 2*c;
            float2 v0; v0.x = acc[mt][nt][0] + b0v; v0.y = acc[mt][nt][1] + b0v;
            float2 v1; v1.x = acc[mt][nt][2] + b1v; v1.y = acc[mt][nt][3] + b1v;
            *(float2*)(o0 + px) = v0;
            *(float2*)(o1 + px) = v1;
        }
    }
}

// ---------------- tiny FFMA2 conv for the 16->2 head -----------------------
#define C_NT 128
#define C_TH 16
#define C_TW 64
#define C_CO 8

template<int DIL>
__global__ __launch_bounds__(C_NT, 3)
void conv3x3_kernel(const float* __restrict__ in, int Cin, int CinS, int cinOff,
                    const float* __restrict__ wgt, const float* __restrict__ bias,
                    float* __restrict__ out, int Cout, int CoutS, int coutOff)
{
    constexpr int TLW = C_TW + 2*DIL;
    constexpr int TLH = C_TH + 2*DIL;
    constexpr int NE  = (DIL==1) ? 5 : (DIL==2) ? 6 : 8;
    __shared__ __align__(16) float s_in[2][TLH*TLW];
    __shared__ __align__(16) ull   s_w2[2][C_CO*9];

    const int cb   = blockIdx.x * C_CO;
    const int tile = blockIdx.y;
    const int x0g  = (tile & 3) * C_TW;
    const int y0g  = (tile >> 2) * C_TH;
    const int b    = blockIdx.z;
    const int tid  = threadIdx.x;
    const int ty   = tid >> 3;
    const int xo   = (tid & 7) * 8;

    ull acc[C_CO][4];
#pragma unroll
    for (int co=0;co<C_CO;co++)
#pragma unroll
        for (int p=0;p<4;p++) acc[co][p] = 0ull;

    for (int ci0 = 0; ci0 < Cin; ci0 += 2) {
#pragma unroll
        for (int cc = 0; cc < 2; cc++) {
            const int ci = ci0 + cc;
            const float* ip = in + ((size_t)(b*CinS + cinOff + ci))*HWSZ;
            const bool cv = (ci < Cin);
            for (int idx = tid; idx < TLH*TLW; idx += C_NT) {
                int r = idx / TLW, cx = idx - r*TLW;
                int gy = y0g + r - DIL, gx = x0g + cx - DIL;
                float v = 0.f;
                if (cv && gy >= 0 && gy < HH && gx >= 0 && gx < WW) v = ip[gy*WW + gx];
                s_in[cc][idx] = v;
            }
        }
        for (int idx = tid; idx < 2*C_CO*9; idx += C_NT) {
            int cc = idx / (C_CO*9);
            int t  = idx - cc*(C_CO*9);
            int co = t / 9, k = t - co*9;
            int gci = ci0 + cc, gco = cb + co;
            float w = (gci < Cin && gco < Cout) ? wgt[((size_t)gco*Cin + gci)*9 + k] : 0.f;
            s_w2[cc][t] = pk2(w, w);
        }
        __syncthreads();
#pragma unroll
        for (int cc = 0; cc < 2; cc++) {
#pragma unroll
            for (int ky = 0; ky < 3; ky++) {
                const float* rowp = &s_in[cc][(ty + ky*DIL)*TLW + xo];
                ull E[NE];
#pragma unroll
                for (int i = 0; i < NE; i++) E[i] = *(const ull*)(rowp + 2*i);
                ull O[4];
                if (DIL == 1) {
#pragma unroll
                    for (int i = 0; i < 4; i++) O[i] = pk2(rowp[2*i+1], rowp[2*i+2]);
                }
#pragma unroll
                for (int kx = 0; kx < 3; kx++) {
                    ull vv[4];
                    if (DIL == 1) {
                        if (kx == 0)      { vv[0]=E[0]; vv[1]=E[1]; vv[2]=E[2]; vv[3]=E[3]; }
                        else if (kx == 1) { vv[0]=O[0]; vv[1]=O[1]; vv[2]=O[2]; vv[3]=O[3]; }
                        else              { vv[0]=E[1]; vv[1]=E[2]; vv[2]=E[3]; vv[3]=E[4]; }
                    } else {
                        const int base = kx*(DIL/2);
#pragma unroll
                        for (int p = 0; p < 4; p++) vv[p] = E[base + p];
                    }
#pragma unroll
                    for (int co = 0; co < C_CO; co++) {
                        ull w = s_w2[cc][co*9 + ky*3 + kx];
#pragma unroll
                        for (int p = 0; p < 4; p++) fma2(acc[co][p], w, vv[p]);
                    }
                }
            }
        }
        __syncthreads();
    }
#pragma unroll
    for (int co = 0; co < C_CO; co++) {
        int gco = cb + co;
        if (gco >= Cout) break;
        float bv = bias ? bias[gco] : 0.f;
        ull bv2 = pk2(bv, bv);
        float* op = out + ((size_t)(b*CoutS + coutOff + gco))*HWSZ + (y0g + ty)*WW + x0g + xo;
#pragma unroll
        for (int p = 0; p < 4; p++) {
            ull r = add2(acc[co][p], bv2);
            *(ull*)(op + 2*p) = r;
        }
    }
}

// ---------------- instance norm + leaky relu (in place, float4) ----------
__global__ void instnorm_lrelu_kernel(float* __restrict__ x, const float* __restrict__ gamma,
                                      const float* __restrict__ beta, int C)
{
    const int bc = blockIdx.x;
    float4* p = (float4*)(x + (size_t)bc*HWSZ);
    const int N4 = HWSZ/4;
    const int tid = threadIdx.x;
    float s = 0.f, s2 = 0.f;
    for (int i = tid; i < N4; i += 256) {
        float4 v = p[i];
        s  += v.x + v.y + v.z + v.w;
        s2 += v.x*v.x + v.y*v.y + v.z*v.z + v.w*v.w;
    }
    __shared__ float rs[256], rq[256];
    rs[tid] = s; rq[tid] = s2; __syncthreads();
    for (int off = 128; off > 0; off >>= 1) {
        if (tid < off) { rs[tid] += rs[tid+off]; rq[tid] += rq[tid+off]; }
        __syncthreads();
    }
    const float mu  = rs[0]*(1.f/HWSZ);
    const float var = rq[0]*(1.f/HWSZ) - mu*mu;
    const float inv = rsqrtf(var + 1e-5f);
    const int c = bc % C;
    const float ga = gamma[c]*inv, be = beta[c];
    for (int i = tid; i < N4; i += 256) {
        float4 v = p[i];
        v.x = (v.x-mu)*ga + be; v.x = (v.x >= 0.f) ? v.x : 0.2f*v.x;
        v.y = (v.y-mu)*ga + be; v.y = (v.y >= 0.f) ? v.y : 0.2f*v.y;
        v.z = (v.z-mu)*ga + be; v.z = (v.z >= 0.f) ? v.z : 0.2f*v.z;
        v.w = (v.w-mu)*ga + be; v.w = (v.w >= 0.f) ? v.w : 0.2f*v.w;
        p[i] = v;
    }
}

// ---------------- separable gaussian blur, replicate padding ------------
__global__ void blur_h_kernel(const float* __restrict__ in, int CinS, int cinOff,
                              float* __restrict__ out, int C, int n)
{
    int idx = blockIdx.x*blockDim.x + threadIdx.x;
    if (idx >= n) return;
    int x = idx % WW;
    int y = (idx / WW) % HH;
    int bc = idx / HWSZ;
    int b = bc / C, c = bc % C;
    const float* ip = in + ((size_t)(b*CinS + cinOff + c))*HWSZ + y*WW;
    float s = 0.f;
#pragma unroll
    for (int t = 0; t < 7; t++) {
        int xx = x + t - 3;
        xx = min(max(xx, 0), WW-1);
        s += GK[t]*ip[xx];
    }
    out[(size_t)bc*HWSZ + y*WW + x] = s;
}

__global__ void blur_v_kernel(const float* __restrict__ in, float* __restrict__ out, int n)
{
    int idx = blockIdx.x*blockDim.x + threadIdx.x;
    if (idx >= n) return;
    int x = idx % WW;
    int y = (idx / WW) % HH;
    int bc = idx / HWSZ;
    const float* ip = in + (size_t)bc*HWSZ;
    float s = 0.f;
#pragma unroll
    for (int t = 0; t < 7; t++) {
        int yy = y + t - 3;
        yy = min(max(yy, 0), HH-1);
        s += GK[t]*ip[yy*WW + x];
    }
    out[(size_t)bc*HWSZ + y*WW + x] = s;
}

// ---------------- local correlation ----------------
__global__ void corr_kernel(const float* __restrict__ f1s, const float* __restrict__ f2base,
                            float* __restrict__ out, float* __restrict__ lcsum)
{
    __shared__ float s1[22*22];
    __shared__ float red[256];
    const int bx = blockIdx.x, by = blockIdx.y, b = blockIdx.z;
    const int tid = threadIdx.x;
    const int ty = tid >> 4, tx = tid & 15;
    const int gy = by*16 + ty, gx = bx*16 + tx;

    float acc[49];
#pragma unroll
    for (int k = 0; k < 49; k++) acc[k] = 0.f;

    for (int c = 0; c < 64; c++) {
        const float* p1 = f1s    + ((size_t)(b*64  + c))*HWSZ;
        const float* p2 = f2base + ((size_t)(b*128 + 64 + c))*HWSZ;
        for (int idx = tid; idx < 22*22; idx += 256) {
            int r = idx/22, cc = idx%22;
            int yy = by*16 + r - 3, xx = bx*16 + cc - 3;
            s1[idx] = (yy >= 0 && yy < HH && xx >= 0 && xx < WW) ? p1[yy*WW+xx] : 0.f;
        }
        __syncthreads();
        const float v2 = p2[gy*WW + gx];
#pragma unroll
        for (int i = 0; i < 7; i++) {
#pragma unroll
            for (int j = 0; j < 7; j++) {
                float d = v2 - s1[(ty+i)*22 + tx+j];
                acc[i*7+j] += d*d;
            }
        }
        __syncthreads();
    }
    float tsum = 0.f;
#pragma unroll
    for (int k = 0; k < 49; k++) {
        float lc = acc[k]*(1.f/64.f);
        out[((size_t)(b*128 + 64 + k))*HWSZ + gy*WW + gx] = lc;
        tsum += lc;
    }
    red[tid] = tsum; __syncthreads();
    for (int off = 128; off > 0; off >>= 1) {
        if (tid < off) red[tid] += red[tid+off];
        __syncthreads();
    }
    if (tid == 0) atomicAdd(&lcsum[b], red[0]);
}

__global__ void zero_lcsum_kernel(float* lcsum)
{
    if (threadIdx.x < BB) lcsum[threadIdx.x] = 0.f;
}

__global__ void lcnorm_kernel(float* __restrict__ corr, const float* __restrict__ lcsum, int n)
{
    int idx = blockIdx.x*blockDim.x + threadIdx.x;
    if (idx >= n) return;
    int b = idx / (49*HWSZ);
    int r = idx - b*(49*HWSZ);
    float mean = lcsum[b]*(1.f/(49.f*HWSZ));
    float s = 1.f/(mean + 1e-6f);
    corr[((size_t)b*128 + 64)*HWSZ + r] *= s;
}

// ---------------- host side ----------------
template<int COUT, int CIN, int DIL>
static void launch_mma(const float* in, int CinS, int cinOff,
                       const float* wp, const float* bias,
                       float* out, int CoutS, int coutOff)
{
    constexpr int NROWS = 2 + 2*DIL;
    const int smem = (NROWS*KC*PWD + 9*KC*(COUT+8))*4;
    cudaFuncSetAttribute(conv_mma<COUT,CIN,DIL>,
                         cudaFuncAttributeMaxDynamicSharedMemorySize, smem);
    conv_mma<COUT,CIN,DIL><<<dim3(2, HH/2, BB), 512, smem>>>(
        in, CinS, cinOff, wp, bias, out, CoutS, coutOff);
}

extern "C" void kernel_launch(void* const* d_in, const int* in_sizes, int n_in,
                              void* d_out, int out_size)
{
    const float* feat1  = (const float*)d_in[0];
    const float* feat2  = (const float*)d_in[1];
    const float* pre_w  = (const float*)d_in[2];
    const float* pre_b  = (const float*)d_in[3];
    const float* fc1_w  = (const float*)d_in[4];
    const float* fc1_g  = (const float*)d_in[5];
    const float* fc1_be = (const float*)d_in[6];
    const float* fc2_w  = (const float*)d_in[7];
    const float* fc2_b  = (const float*)d_in[8];
    const float* e1_w   = (const float*)d_in[9];
    const float* e1_g   = (const float*)d_in[10];
    const float* e1_be  = (const float*)d_in[11];
    const float* e2_w   = (const float*)d_in[12];
    const float* e2_g   = (const float*)d_in[13];
    const float* e2_be  = (const float*)d_in[14];
    const float* e3_w   = (const float*)d_in[15];
    const float* e3_g   = (const float*)d_in[16];
    const float* e3_be  = (const float*)d_in[17];
    const float* head_w = (const float*)d_in[18];
    const float* head_b = (const float*)d_in[19];
    float* out = (float*)d_out;

    float *cat_, *x128, *corr_, *f1s, *tmp_, *x64, *x32, *x16, *head_, *lcsum, *wpb;
    cudaGetSymbolAddress((void**)&cat_,  g_cat);
    cudaGetSymbolAddress((void**)&x128,  g_x128);
    cudaGetSymbolAddress((void**)&corr_, g_corr);
    cudaGetSymbolAddress((void**)&f1s,   g_f1s);
    cudaGetSymbolAddress((void**)&tmp_,  g_tmp);
    cudaGetSymbolAddress((void**)&x64,   g_x64);
    cudaGetSymbolAddress((void**)&x32,   g_x32);
    cudaGetSymbolAddress((void**)&x16,   g_x16);
    cudaGetSymbolAddress((void**)&head_, g_head);
    cudaGetSymbolAddress((void**)&lcsum, g_lcsum);
    cudaGetSymbolAddress((void**)&wpb,   g_wp);

    float* wp_pre = wpb;
    float* wp_fc1 = wpb + 36864;
    float* wp_fc2 = wpb + 184320;
    float* wp_e1  = wpb + 258048;
    float* wp_e2  = wpb + 331776;
    float* wp_e3  = wpb + 350208;

    // weight prep (reorder + tf32 round + ci pad)
    prep_w_kernel<<<(9*64*64   + 255)/256, 256>>>(pre_w, wp_pre, 64, 64, 64);
    prep_w_kernel<<<(9*128*128 + 255)/256, 256>>>(fc1_w, wp_fc1, 128, 128, 128);
    prep_w_kernel<<<(9*128*64  + 255)/256, 256>>>(fc2_w, wp_fc2, 64, 128, 128);
    prep_w_kernel<<<(9*128*64  + 255)/256, 256>>>(e1_w,  wp_e1,  64, 113, 128);
    prep_w_kernel<<<(9*64*32   + 255)/256, 256>>>(e2_w,  wp_e2,  32, 64, 64);
    prep_w_kernel<<<(9*32*16   + 255)/256, 256>>>(e3_w,  wp_e3,  16, 32, 32);

    // preprocessor (shared weights) -> concat buffer
    launch_mma<64,64,1>(feat1, 64, 0, wp_pre, pre_b, cat_, 128, 0);
    launch_mma<64,64,1>(feat2, 64, 0, wp_pre, pre_b, cat_, 128, 64);

    // featcompressor layer1 + IN + lrelu
    launch_mma<128,128,1>(cat_, 128, 0, wp_fc1, nullptr, x128, 128, 0);
    instnorm_lrelu_kernel<<<BB*128, 256>>>(x128, fc1_g, fc1_be, 128);

    // featcompressor layer2 -> corr channels 0..63
    launch_mma<64,128,1>(x128, 128, 0, wp_fc2, fc2_b, corr_, 128, 0);

    // gaussian blur of f1 (replicate pad, separable)
    {
        int n = BB*64*HWSZ;
        blur_h_kernel<<<(n+255)/256, 256>>>(cat_, 128, 0, tmp_, 64, n);
        blur_v_kernel<<<(n+255)/256, 256>>>(tmp_, f1s, n);
    }

    // local correlation -> corr channels 64..112, then normalize by batch mean
    zero_lcsum_kernel<<<1, 32>>>(lcsum);
    corr_kernel<<<dim3(WW/16, HH/16, BB), 256>>>(f1s, cat_, corr_, lcsum);
    {
        int n = BB*49*HWSZ;
        lcnorm_kernel<<<(n+255)/256, 256>>>(corr_, lcsum, n);
    }

    // estimator stack (e1 reads 128-ch corr; weights zero-padded for ci>=113)
    launch_mma<64,128,1>(corr_, 128, 0, wp_e1, nullptr, x64, 64, 0);
    instnorm_lrelu_kernel<<<BB*64, 256>>>(x64, e1_g, e1_be, 64);

    launch_mma<32,64,2>(x64, 64, 0, wp_e2, nullptr, x32, 32, 0);
    instnorm_lrelu_kernel<<<BB*32, 256>>>(x32, e2_g, e2_be, 32);

    launch_mma<16,32,4>(x32, 32, 0, wp_e3, nullptr, x16, 16, 0);
    instnorm_lrelu_kernel<<<BB*16, 256>>>(x16, e3_g, e3_be, 16);

    // flow head (tiny, FFMA2 direct conv)
    {
        dim3 grid(1, (WW/C_TW)*(HH/C_TH), BB);
        conv3x3_kernel<1><<<grid, C_NT>>>(x16, 16, 16, 0, head_w, head_b, head_, 2, 2, 0);
    }

    // final blur -> output
    {
        int n = BB*2*HWSZ;
        blur_h_kernel<<<(n+255)/256, 256>>>(head_, 2, 0, tmp_, 2, n);
        blur_v_kernel<<<(n+255)/256, 256>>>(tmp_, out, n);
    }
}

// round 6
// speedup vs baseline: 1.1419x; 1.1419x over previous
#include <cuda_runtime.h>
#include <math.h>

// ---------------- problem constants ----------------
#define BB 4
#define HH 256
#define WW 256
#define HWSZ (HH*WW)

typedef unsigned long long ull;

// ---------------- scratch buffers ----------------
__device__ float g_cat [(size_t)BB*128*HWSZ];  // f1 (ch0..63) | f2 (ch64..127)
__device__ float g_x128[(size_t)BB*128*HWSZ];  // fc1 output
__device__ float g_corr[(size_t)BB*128*HWSZ];  // feat (0..63) | lc (64..112) | zero pad
__device__ float g_f1s [(size_t)BB*64*HWSZ];   // blurred f1
__device__ float g_tmp [(size_t)BB*64*HWSZ];   // blur horizontal pass scratch
__device__ float g_x64 [(size_t)BB*64*HWSZ];
__device__ float g_x32 [(size_t)BB*32*HWSZ];
__device__ float g_x16 [(size_t)BB*16*HWSZ];
__device__ float g_head[(size_t)BB*2*HWSZ];
__device__ float g_lcsum[BB];
// prepped (reordered + tf32-rounded, ci-padded) weights
__device__ float g_wp[36864 + 147456 + 73728 + 73728 + 18432 + 4608];

// gaussian 1d kernel (sigma=1.5, size 7)
__constant__ float GK[7] = {0.03663285f, 0.11128102f, 0.21674443f, 0.27068263f,
                            0.21674443f, 0.11128102f, 0.03663285f};

// ---------------- helpers ----------------
__device__ __forceinline__ unsigned f2tf(float f) {
    unsigned r; asm("cvt.rna.tf32.f32 %0, %1;" : "=r"(r) : "f"(f)); return r;
}
__device__ __forceinline__ void mma8(float* d, const unsigned* a, const unsigned* b) {
    asm volatile("mma.sync.aligned.m16n8k8.row.col.f32.tf32.tf32.f32 "
        "{%0,%1,%2,%3}, {%4,%5,%6,%7}, {%8,%9}, {%0,%1,%2,%3};\n"
        : "+f"(d[0]), "+f"(d[1]), "+f"(d[2]), "+f"(d[3])
        : "r"(a[0]), "r"(a[1]), "r"(a[2]), "r"(a[3]), "r"(b[0]), "r"(b[1]));
}
__device__ __forceinline__ ull pk2(float lo, float hi) {
    ull r; asm("mov.b64 %0, {%1, %2};" : "=l"(r) : "f"(lo), "f"(hi)); return r;
}
__device__ __forceinline__ void fma2(ull& d, ull a, ull b) {
    asm("fma.rn.f32x2 %0, %1, %2, %0;" : "+l"(d) : "l"(a), "l"(b));
}
__device__ __forceinline__ ull add2(ull a, ull b) {
    ull r; asm("add.rn.f32x2 %0, %1, %2;" : "=l"(r) : "l"(a), "l"(b)); return r;
}
__device__ __forceinline__ unsigned smem_u32(const void* p) {
    return (unsigned)__cvta_generic_to_shared(p);
}
__device__ __forceinline__ void cpasync16(unsigned dst, const void* src) {
    asm volatile("cp.async.cg.shared.global [%0], [%1], 16;" :: "r"(dst), "l"(src));
}

// ---------------- merged weight prep ---------------------------------------
// OIHW -> [k9][CINP][COUT], tf32-rounded, ci zero-padded; all 6 layers.
__global__ void prep_all_kernel(const float* __restrict__ w_pre,
                                const float* __restrict__ w_fc1,
                                const float* __restrict__ w_fc2,
                                const float* __restrict__ w_e1,
                                const float* __restrict__ w_e2,
                                const float* __restrict__ w_e3,
                                float* __restrict__ wp)
{
    int idx = blockIdx.x*256 + threadIdx.x;
    const float* src; int COUT, CIN, CINP, r;
    if      (idx < 36864)  { src=w_pre; COUT=64;  CIN=64;  CINP=64;  r=idx; }
    else if (idx < 184320) { src=w_fc1; COUT=128; CIN=128; CINP=128; r=idx-36864; }
    else if (idx < 258048) { src=w_fc2; COUT=64;  CIN=128; CINP=128; r=idx-184320; }
    else if (idx < 331776) { src=w_e1;  COUT=64;  CIN=113; CINP=128; r=idx-258048; }
    else if (idx < 350208) { src=w_e2;  COUT=32;  CIN=64;  CINP=64;  r=idx-331776; }
    else if (idx < 354816) { src=w_e3;  COUT=16;  CIN=32;  CINP=32;  r=idx-350208; }
    else return;
    int co = r % COUT;
    int t  = r / COUT;
    int ci = t % CINP;
    int k9 = t / CINP;
    float v = (ci < CIN) ? src[((size_t)(co*CIN + ci))*9 + k9] : 0.f;
    wp[idx] = __uint_as_float(f2tf(v));
}

// ---------------- tf32 tensor-core 3x3 conv (R4 config) --------------------
// CTA = 256 threads, computes 128-pixel row strip x COUT channels.
#define KC 16
#define PWD 136   // padded smem row width (136 % 32 == 8 -> conflict-free)

template<int COUT, int CIN, int DIL>
__global__ __launch_bounds__(256)
void conv_mma(const float* __restrict__ in, int CinS, int cinOff,
              const float* __restrict__ wp, const float* __restrict__ bias,
              float* __restrict__ out, int CoutS, int coutOff)
{
    constexpr int WM = (COUT >= 32) ? 32 : COUT;
    constexpr int NMW = COUT / WM;
    constexpr int NNW = 8 / NMW;
    constexpr int WN  = 128 / NNW;
    constexpr int MTILES = WM / 16;
    constexpr int NTILES = WN / 8;
    constexpr int CP  = COUT + 8;
    constexpr int PWU = 128 + 2*DIL;

    extern __shared__ __align__(16) unsigned smem_u[];
    unsigned* s_in = smem_u;                    // [3][KC][PWD]
    unsigned* s_w  = smem_u + 3*KC*PWD;         // [9][KC][CP]

    const int tid = threadIdx.x;
    const int x0  = blockIdx.x * 128;
    const int y   = blockIdx.y;
    const int bz  = blockIdx.z;
    const int wid = tid >> 5, lane = tid & 31;
    const int g = lane >> 2, c = lane & 3;
    const int wm = wid % NMW, wn = wid / NMW;

    float acc[MTILES][NTILES][4];
#pragma unroll
    for (int mt=0; mt<MTILES; mt++)
#pragma unroll
        for (int nt=0; nt<NTILES; nt++)
#pragma unroll
            for (int r=0; r<4; r++) acc[mt][nt][r] = 0.f;

    const bool interior = (y >= DIL) && (y + DIL < HH) &&
                          (x0 >= DIL) && (x0 + 128 + DIL <= WW);

#pragma unroll 1
    for (int ci0 = 0; ci0 < CIN; ci0 += KC) {
        __syncthreads();
        // async weight prefetch [9][KC][CP] (pure copy; already tf32 in gmem)
        {
            constexpr int NW4 = 9*KC*(COUT/4);
            const float4* wp4base = (const float4*)wp;
            for (int idx = tid; idx < NW4; idx += 256) {
                int co4 = idx % (COUT/4);
                int t   = idx / (COUT/4);
                int ci  = t % KC;
                int k9  = t / KC;
                unsigned dst = smem_u32((float*)s_w + (k9*KC + ci)*CP + co4*4);
                cpasync16(dst, wp4base + ((size_t)(k9*CIN + ci0 + ci))*(COUT/4) + co4);
            }
            asm volatile("cp.async.commit_group;");
        }
        // fill input strip (3 rows x KC ch x PWU px), zero pad at borders
        if (interior) {
            constexpr int FILLN = 3*KC*PWU;
            for (int idx = tid; idx < FILLN; idx += 256) {
                int px  = idx % PWU;
                int t   = idx / PWU;
                int ci  = t % KC;
                int row = t / KC;
                float v = in[((size_t)(bz*CinS + cinOff + ci0 + ci))*HWSZ
                             + (size_t)(y + (row-1)*DIL)*WW + (x0 - DIL + px)];
                s_in[(row*KC + ci)*PWD + px] = f2tf(v);
            }
        } else {
            constexpr int FILLN = 3*KC*PWU;
            for (int idx = tid; idx < FILLN; idx += 256) {
                int px  = idx % PWU;
                int t   = idx / PWU;
                int ci  = t % KC;
                int row = t / KC;
                int gy = y + (row-1)*DIL;
                int gx = x0 - DIL + px;
                float v = 0.f;
                if (gy >= 0 && gy < HH && gx >= 0 && gx < WW)
                    v = in[((size_t)(bz*CinS + cinOff + ci0 + ci))*HWSZ + (size_t)gy*WW + gx];
                s_in[(row*KC + ci)*PWD + px] = f2tf(v);
            }
        }
        asm volatile("cp.async.wait_group 0;" ::: "memory");
        __syncthreads();

#pragma unroll
        for (int ky=0; ky<3; ky++) {
#pragma unroll
            for (int kx=0; kx<3; kx++) {
                const int xoff = kx*DIL + wn*WN;
#pragma unroll
                for (int ks=0; ks<KC/8; ks++) {
                    unsigned a[MTILES][4];
#pragma unroll
                    for (int mt=0; mt<MTILES; mt++) {
                        const unsigned* wb = s_w + ((ky*3+kx)*KC + ks*8 + c)*CP + wm*WM + mt*16 + g;
                        a[mt][0] = wb[0];
                        a[mt][1] = wb[8];
                        a[mt][2] = wb[4*CP];
                        a[mt][3] = wb[4*CP + 8];
                    }
#pragma unroll
                    for (int nt=0; nt<NTILES; nt++) {
                        const unsigned* bb = s_in + (ky*KC + ks*8 + c)*PWD + xoff + nt*8 + g;
                        unsigned bv[2];
                        bv[0] = bb[0];
                        bv[1] = bb[4*PWD];
#pragma unroll
                        for (int mt=0; mt<MTILES; mt++)
                            mma8(acc[mt][nt], a[mt], bv);
                    }
                }
            }
        }
    }

    // epilogue -> NCHW
#pragma unroll
    for (int mt=0; mt<MTILES; mt++) {
        const int co0 = wm*WM + mt*16 + g;
        const float b0v = bias ? bias[co0]     : 0.f;
        const float b1v = bias ? bias[co0 + 8] : 0.f;
        float* o0 = out + ((size_t)(bz*CoutS + coutOff + co0))*HWSZ + (size_t)y*WW + x0 + wn*WN;
        float* o1 = o0 + (size_t)8*HWSZ;
#pragma unroll
        for (int nt=0; nt<NTILES; nt++) {
            const int px = nt*8 + 2*c;
            float2 v0; v0.x = acc[mt][nt][0] + b0v; v0.y = acc[mt][nt][1] + b0v;
            float2 v1; v1.x = acc[mt][nt][2] + b1v; v1.y = acc[mt][nt][3] + b1v;
            *(float2*)(o0 + px) = v0;
            *(float2*)(o1 + px) = v1;
        }
    }
}

// ---------------- tiny FFMA2 conv for the 16->2 head -----------------------
#define C_NT 128
#define C_TH 16
#define C_TW 64
#define C_CO 8

template<int DIL>
__global__ __launch_bounds__(C_NT, 3)
void conv3x3_kernel(const float* __restrict__ in, int Cin, int CinS, int cinOff,
                    const float* __restrict__ wgt, const float* __restrict__ bias,
                    float* __restrict__ out, int Cout, int CoutS, int coutOff)
{
    constexpr int TLW = C_TW + 2*DIL;
    constexpr int TLH = C_TH + 2*DIL;
    constexpr int NE  = (DIL==1) ? 5 : (DIL==2) ? 6 : 8;
    __shared__ __align__(16) float s_in[2][TLH*TLW];
    __shared__ __align__(16) ull   s_w2[2][C_CO*9];

    const int cb   = blockIdx.x * C_CO;
    const int tile = blockIdx.y;
    const int x0g  = (tile & 3) * C_TW;
    const int y0g  = (tile >> 2) * C_TH;
    const int b    = blockIdx.z;
    const int tid  = threadIdx.x;
    const int ty   = tid >> 3;
    const int xo   = (tid & 7) * 8;

    ull acc[C_CO][4];
#pragma unroll
    for (int co=0;co<C_CO;co++)
#pragma unroll
        for (int p=0;p<4;p++) acc[co][p] = 0ull;

    for (int ci0 = 0; ci0 < Cin; ci0 += 2) {
#pragma unroll
        for (int cc = 0; cc < 2; cc++) {
            const int ci = ci0 + cc;
            const float* ip = in + ((size_t)(b*CinS + cinOff + ci))*HWSZ;
            const bool cv = (ci < Cin);
            for (int idx = tid; idx < TLH*TLW; idx += C_NT) {
                int r = idx / TLW, cx = idx - r*TLW;
                int gy = y0g + r - DIL, gx = x0g + cx - DIL;
                float v = 0.f;
                if (cv && gy >= 0 && gy < HH && gx >= 0 && gx < WW) v = ip[gy*WW + gx];
                s_in[cc][idx] = v;
            }
        }
        for (int idx = tid; idx < 2*C_CO*9; idx += C_NT) {
            int cc = idx / (C_CO*9);
            int t  = idx - cc*(C_CO*9);
            int co = t / 9, k = t - co*9;
            int gci = ci0 + cc, gco = cb + co;
            float w = (gci < Cin && gco < Cout) ? wgt[((size_t)gco*Cin + gci)*9 + k] : 0.f;
            s_w2[cc][t] = pk2(w, w);
        }
        __syncthreads();
#pragma unroll
        for (int cc = 0; cc < 2; cc++) {
#pragma unroll
            for (int ky = 0; ky < 3; ky++) {
                const float* rowp = &s_in[cc][(ty + ky*DIL)*TLW + xo];
                ull E[NE];
#pragma unroll
                for (int i = 0; i < NE; i++) E[i] = *(const ull*)(rowp + 2*i);
                ull O[4];
                if (DIL == 1) {
#pragma unroll
                    for (int i = 0; i < 4; i++) O[i] = pk2(rowp[2*i+1], rowp[2*i+2]);
                }
#pragma unroll
                for (int kx = 0; kx < 3; kx++) {
                    ull vv[4];
                    if (DIL == 1) {
                        if (kx == 0)      { vv[0]=E[0]; vv[1]=E[1]; vv[2]=E[2]; vv[3]=E[3]; }
                        else if (kx == 1) { vv[0]=O[0]; vv[1]=O[1]; vv[2]=O[2]; vv[3]=O[3]; }
                        else              { vv[0]=E[1]; vv[1]=E[2]; vv[2]=E[3]; vv[3]=E[4]; }
                    } else {
                        const int base = kx*(DIL/2);
#pragma unroll
                        for (int p = 0; p < 4; p++) vv[p] = E[base + p];
                    }
#pragma unroll
                    for (int co = 0; co < C_CO; co++) {
                        ull w = s_w2[cc][co*9 + ky*3 + kx];
#pragma unroll
                        for (int p = 0; p < 4; p++) fma2(acc[co][p], w, vv[p]);
                    }
                }
            }
        }
        __syncthreads();
    }
#pragma unroll
    for (int co = 0; co < C_CO; co++) {
        int gco = cb + co;
        if (gco >= Cout) break;
        float bv = bias ? bias[gco] : 0.f;
        ull bv2 = pk2(bv, bv);
        float* op = out + ((size_t)(b*CoutS + coutOff + gco))*HWSZ + (y0g + ty)*WW + x0g + xo;
#pragma unroll
        for (int p = 0; p < 4; p++) {
            ull r = add2(acc[co][p], bv2);
            *(ull*)(op + 2*p) = r;
        }
    }
}

// ---------------- instance norm + leaky relu (in place, float4) ----------
__global__ void instnorm_lrelu_kernel(float* __restrict__ x, const float* __restrict__ gamma,
                                      const float* __restrict__ beta, int C)
{
    const int bc = blockIdx.x;
    float4* p = (float4*)(x + (size_t)bc*HWSZ);
    const int N4 = HWSZ/4;
    const int tid = threadIdx.x;
    float s = 0.f, s2 = 0.f;
    for (int i = tid; i < N4; i += 256) {
        float4 v = p[i];
        s  += v.x + v.y + v.z + v.w;
        s2 += v.x*v.x + v.y*v.y + v.z*v.z + v.w*v.w;
    }
    __shared__ float rs[256], rq[256];
    rs[tid] = s; rq[tid] = s2; __syncthreads();
    for (int off = 128; off > 0; off >>= 1) {
        if (tid < off) { rs[tid] += rs[tid+off]; rq[tid] += rq[tid+off]; }
        __syncthreads();
    }
    const float mu  = rs[0]*(1.f/HWSZ);
    const float var = rq[0]*(1.f/HWSZ) - mu*mu;
    const float inv = rsqrtf(var + 1e-5f);
    const int c = bc % C;
    const float ga = gamma[c]*inv, be = beta[c];
    for (int i = tid; i < N4; i += 256) {
        float4 v = p[i];
        v.x = (v.x-mu)*ga + be; v.x = (v.x >= 0.f) ? v.x : 0.2f*v.x;
        v.y = (v.y-mu)*ga + be; v.y = (v.y >= 0.f) ? v.y : 0.2f*v.y;
        v.z = (v.z-mu)*ga + be; v.z = (v.z >= 0.f) ? v.z : 0.2f*v.z;
        v.w = (v.w-mu)*ga + be; v.w = (v.w >= 0.f) ? v.w : 0.2f*v.w;
        p[i] = v;
    }
}

// ---------------- separable gaussian blur, replicate padding ------------
__global__ void blur_h_kernel(const float* __restrict__ in, int CinS, int cinOff,
                              float* __restrict__ out, int C, int n)
{
    int idx = blockIdx.x*blockDim.x + threadIdx.x;
    if (idx >= n) return;
    int x = idx % WW;
    int y = (idx / WW) % HH;
    int bc = idx / HWSZ;
    int b = bc / C, c = bc % C;
    const float* ip = in + ((size_t)(b*CinS + cinOff + c))*HWSZ + y*WW;
    float s = 0.f;
#pragma unroll
    for (int t = 0; t < 7; t++) {
        int xx = x + t - 3;
        xx = min(max(xx, 0), WW-1);
        s += GK[t]*ip[xx];
    }
    out[(size_t)bc*HWSZ + y*WW + x] = s;
}

__global__ void blur_v_kernel(const float* __restrict__ in, float* __restrict__ out, int n)
{
    int idx = blockIdx.x*blockDim.x + threadIdx.x;
    if (idx >= n) return;
    int x = idx % WW;
    int y = (idx / WW) % HH;
    int bc = idx / HWSZ;
    const float* ip = in + (size_t)bc*HWSZ;
    float s = 0.f;
#pragma unroll
    for (int t = 0; t < 7; t++) {
        int yy = y + t - 3;
        yy = min(max(yy, 0), HH-1);
        s += GK[t]*ip[yy*WW + x];
    }
    out[(size_t)bc*HWSZ + y*WW + x] = s;
}

// ---------------- local correlation ----------------
__global__ void corr_kernel(const float* __restrict__ f1s, const float* __restrict__ f2base,
                            float* __restrict__ out, float* __restrict__ lcsum)
{
    __shared__ float s1[22*22];
    __shared__ float red[256];
    const int bx = blockIdx.x, by = blockIdx.y, b = blockIdx.z;
    const int tid = threadIdx.x;
    const int ty = tid >> 4, tx = tid & 15;
    const int gy = by*16 + ty, gx = bx*16 + tx;

    float acc[49];
#pragma unroll
    for (int k = 0; k < 49; k++) acc[k] = 0.f;

    for (int c = 0; c < 64; c++) {
        const float* p1 = f1s    + ((size_t)(b*64  + c))*HWSZ;
        const float* p2 = f2base + ((size_t)(b*128 + 64 + c))*HWSZ;
        for (int idx = tid; idx < 22*22; idx += 256) {
            int r = idx/22, cc = idx%22;
            int yy = by*16 + r - 3, xx = bx*16 + cc - 3;
            s1[idx] = (yy >= 0 && yy < HH && xx >= 0 && xx < WW) ? p1[yy*WW+xx] : 0.f;
        }
        __syncthreads();
        const float v2 = p2[gy*WW + gx];
#pragma unroll
        for (int i = 0; i < 7; i++) {
#pragma unroll
            for (int j = 0; j < 7; j++) {
                float d = v2 - s1[(ty+i)*22 + tx+j];
                acc[i*7+j] += d*d;
            }
        }
        __syncthreads();
    }
    float tsum = 0.f;
#pragma unroll
    for (int k = 0; k < 49; k++) {
        float lc = acc[k]*(1.f/64.f);
        out[((size_t)(b*128 + 64 + k))*HWSZ + gy*WW + gx] = lc;
        tsum += lc;
    }
    red[tid] = tsum; __syncthreads();
    for (int off = 128; off > 0; off >>= 1) {
        if (tid < off) red[tid] += red[tid+off];
        __syncthreads();
    }
    if (tid == 0) atomicAdd(&lcsum[b], red[0]);
}

__global__ void zero_lcsum_kernel(float* lcsum)
{
    if (threadIdx.x < BB) lcsum[threadIdx.x] = 0.f;
}

__global__ void lcnorm_kernel(float* __restrict__ corr, const float* __restrict__ lcsum, int n)
{
    int idx = blockIdx.x*blockDim.x + threadIdx.x;
    if (idx >= n) return;
    int b = idx / (49*HWSZ);
    int r = idx - b*(49*HWSZ);
    float mean = lcsum[b]*(1.f/(49.f*HWSZ));
    float s = 1.f/(mean + 1e-6f);
    corr[((size_t)b*128 + 64)*HWSZ + r] *= s;
}

// ---------------- host side ----------------
template<int COUT, int CIN, int DIL>
static void launch_mma(const float* in, int CinS, int cinOff,
                       const float* wp, const float* bias,
                       float* out, int CoutS, int coutOff)
{
    const int smem = (3*KC*PWD + 9*KC*(COUT+8))*4;
    cudaFuncSetAttribute(conv_mma<COUT,CIN,DIL>,
                         cudaFuncAttributeMaxDynamicSharedMemorySize, smem);
    conv_mma<COUT,CIN,DIL><<<dim3(2, HH, BB), 256, smem>>>(
        in, CinS, cinOff, wp, bias, out, CoutS, coutOff);
}

extern "C" void kernel_launch(void* const* d_in, const int* in_sizes, int n_in,
                              void* d_out, int out_size)
{
    const float* feat1  = (const float*)d_in[0];
    const float* feat2  = (const float*)d_in[1];
    const float* pre_w  = (const float*)d_in[2];
    const float* pre_b  = (const float*)d_in[3];
    const float* fc1_w  = (const float*)d_in[4];
    const float* fc1_g  = (const float*)d_in[5];
    const float* fc1_be = (const float*)d_in[6];
    const float* fc2_w  = (const float*)d_in[7];
    const float* fc2_b  = (const float*)d_in[8];
    const float* e1_w   = (const float*)d_in[9];
    const float* e1_g   = (const float*)d_in[10];
    const float* e1_be  = (const float*)d_in[11];
    const float* e2_w   = (const float*)d_in[12];
    const float* e2_g   = (const float*)d_in[13];
    const float* e2_be  = (const float*)d_in[14];
    const float* e3_w   = (const float*)d_in[15];
    const float* e3_g   = (const float*)d_in[16];
    const float* e3_be  = (const float*)d_in[17];
    const float* head_w = (const float*)d_in[18];
    const float* head_b = (const float*)d_in[19];
    float* out = (float*)d_out;

    float *cat_, *x128, *corr_, *f1s, *tmp_, *x64, *x32, *x16, *head_, *lcsum, *wpb;
    cudaGetSymbolAddress((void**)&cat_,  g_cat);
    cudaGetSymbolAddress((void**)&x128,  g_x128);
    cudaGetSymbolAddress((void**)&corr_, g_corr);
    cudaGetSymbolAddress((void**)&f1s,   g_f1s);
    cudaGetSymbolAddress((void**)&tmp_,  g_tmp);
    cudaGetSymbolAddress((void**)&x64,   g_x64);
    cudaGetSymbolAddress((void**)&x32,   g_x32);
    cudaGetSymbolAddress((void**)&x16,   g_x16);
    cudaGetSymbolAddress((void**)&head_, g_head);
    cudaGetSymbolAddress((void**)&lcsum, g_lcsum);
    cudaGetSymbolAddress((void**)&wpb,   g_wp);

    float* wp_pre = wpb;
    float* wp_fc1 = wpb + 36864;
    float* wp_fc2 = wpb + 184320;
    float* wp_e1  = wpb + 258048;
    float* wp_e2  = wpb + 331776;
    float* wp_e3  = wpb + 350208;

    // single merged weight prep (reorder + tf32 round + ci pad)
    prep_all_kernel<<<(354816 + 255)/256, 256>>>(pre_w, fc1_w, fc2_w, e1_w, e2_w, e3_w, wpb);

    // preprocessor (shared weights) -> concat buffer
    launch_mma<64,64,1>(feat1, 64, 0, wp_pre, pre_b, cat_, 128, 0);
    launch_mma<64,64,1>(feat2, 64, 0, wp_pre, pre_b, cat_, 128, 64);

    // featcompressor layer1 + IN + lrelu
    launch_mma<128,128,1>(cat_, 128, 0, wp_fc1, nullptr, x128, 128, 0);
    instnorm_lrelu_kernel<<<BB*128, 256>>>(x128, fc1_g, fc1_be, 128);

    // featcompressor layer2 -> corr channels 0..63
    launch_mma<64,128,1>(x128, 128, 0, wp_fc2, fc2_b, corr_, 128, 0);

    // gaussian blur of f1 (replicate pad, separable)
    {
        int n = BB*64*HWSZ;
        blur_h_kernel<<<(n+255)/256, 256>>>(cat_, 128, 0, tmp_, 64, n);
        blur_v_kernel<<<(n+255)/256, 256>>>(tmp_, f1s, n);
    }

    // local correlation -> corr channels 64..112, then normalize by batch mean
    zero_lcsum_kernel<<<1, 32>>>(lcsum);
    corr_kernel<<<dim3(WW/16, HH/16, BB), 256>>>(f1s, cat_, corr_, lcsum);
    {
        int n = BB*49*HWSZ;
        lcnorm_kernel<<<(n+255)/256, 256>>>(corr_, lcsum, n);
    }

    // estimator stack (e1 reads 128-ch corr; weights zero-padded for ci>=113)
    launch_mma<64,128,1>(corr_, 128, 0, wp_e1, nullptr, x64, 64, 0);
    instnorm_lrelu_kernel<<<BB*64, 256>>>(x64, e1_g, e1_be, 64);

    launch_mma<32,64,2>(x64, 64, 0, wp_e2, nullptr, x32, 32, 0);
    instnorm_lrelu_kernel<<<BB*32, 256>>>(x32, e2_g, e2_be, 32);

    launch_mma<16,32,4>(x32, 32, 0, wp_e3, nullptr, x16, 16, 0);
    instnorm_lrelu_kernel<<<BB*16, 256>>>(x16, e3_g, e3_be, 16);

    // flow head (tiny, FFMA2 direct conv)
    {
        dim3 grid(1, (WW/C_TW)*(HH/C_TH), BB);
        conv3x3_kernel<1><<<grid, C_NT>>>(x16, 16, 16, 0, head_w, head_b, head_, 2, 2, 0);
    }

    // final blur -> output
    {
        int n = BB*2*HWSZ;
        blur_h_kernel<<<(n+255)/256, 256>>>(head_, 2, 0, tmp_, 2, n);
        blur_v_kernel<<<(n+255)/256, 256>>>(tmp_, out, n);
    }
}

// round 7
// speedup vs baseline: 1.3940x; 1.2208x over previous
#include <cuda_runtime.h>
#include <math.h>

// ---------------- problem constants ----------------
#define BB 4
#define HH 256
#define WW 256
#define HWSZ (HH*WW)

typedef unsigned long long ull;

// ---------------- scratch buffers ----------------
__device__ float g_cat [(size_t)BB*128*HWSZ];  // f1 (ch0..63) | f2 (ch64..127)
__device__ float g_x128[(size_t)BB*128*HWSZ];  // fc1 output
__device__ float g_corr[(size_t)BB*128*HWSZ];  // feat (0..63) | lc (64..112) | zero pad
__device__ float g_f1s [(size_t)BB*64*HWSZ];   // blurred f1
__device__ float g_tmp [(size_t)BB*64*HWSZ];   // blur horizontal pass scratch
__device__ float g_x64 [(size_t)BB*64*HWSZ];
__device__ float g_x32 [(size_t)BB*32*HWSZ];
__device__ float g_x16 [(size_t)BB*16*HWSZ];
__device__ float g_head[(size_t)BB*2*HWSZ];
__device__ float g_lcsum[BB];
// prepped (reordered + tf32-rounded, ci-padded) weights
__device__ float g_wp[36864 + 147456 + 73728 + 73728 + 18432 + 4608];

// gaussian 1d kernel (sigma=1.5, size 7)
__constant__ float GK[7] = {0.03663285f, 0.11128102f, 0.21674443f, 0.27068263f,
                            0.21674443f, 0.11128102f, 0.03663285f};

// ---------------- helpers ----------------
__device__ __forceinline__ unsigned f2tf(float f) {
    unsigned r; asm("cvt.rna.tf32.f32 %0, %1;" : "=r"(r) : "f"(f)); return r;
}
__device__ __forceinline__ void mma8(float* d, const unsigned* a, const unsigned* b) {
    asm volatile("mma.sync.aligned.m16n8k8.row.col.f32.tf32.tf32.f32 "
        "{%0,%1,%2,%3}, {%4,%5,%6,%7}, {%8,%9}, {%0,%1,%2,%3};\n"
        : "+f"(d[0]), "+f"(d[1]), "+f"(d[2]), "+f"(d[3])
        : "r"(a[0]), "r"(a[1]), "r"(a[2]), "r"(a[3]), "r"(b[0]), "r"(b[1]));
}
__device__ __forceinline__ ull pk2(float lo, float hi) {
    ull r; asm("mov.b64 %0, {%1, %2};" : "=l"(r) : "f"(lo), "f"(hi)); return r;
}
__device__ __forceinline__ void fma2(ull& d, ull a, ull b) {
    asm("fma.rn.f32x2 %0, %1, %2, %0;" : "+l"(d) : "l"(a), "l"(b));
}
__device__ __forceinline__ ull add2(ull a, ull b) {
    ull r; asm("add.rn.f32x2 %0, %1, %2;" : "=l"(r) : "l"(a), "l"(b)); return r;
}
__device__ __forceinline__ unsigned smem_u32(const void* p) {
    return (unsigned)__cvta_generic_to_shared(p);
}
__device__ __forceinline__ void cpasync16(unsigned dst, const void* src) {
    asm volatile("cp.async.cg.shared.global [%0], [%1], 16;" :: "r"(dst), "l"(src));
}

// ---------------- merged weight prep ---------------------------------------
__global__ void prep_all_kernel(const float* __restrict__ w_pre,
                                const float* __restrict__ w_fc1,
                                const float* __restrict__ w_fc2,
                                const float* __restrict__ w_e1,
                                const float* __restrict__ w_e2,
                                const float* __restrict__ w_e3,
                                float* __restrict__ wp)
{
    int idx = blockIdx.x*256 + threadIdx.x;
    const float* src; int COUT, CIN, CINP, r;
    if      (idx < 36864)  { src=w_pre; COUT=64;  CIN=64;  CINP=64;  r=idx; }
    else if (idx < 184320) { src=w_fc1; COUT=128; CIN=128; CINP=128; r=idx-36864; }
    else if (idx < 258048) { src=w_fc2; COUT=64;  CIN=128; CINP=128; r=idx-184320; }
    else if (idx < 331776) { src=w_e1;  COUT=64;  CIN=113; CINP=128; r=idx-258048; }
    else if (idx < 350208) { src=w_e2;  COUT=32;  CIN=64;  CINP=64;  r=idx-331776; }
    else if (idx < 354816) { src=w_e3;  COUT=16;  CIN=32;  CINP=32;  r=idx-350208; }
    else return;
    int co = r % COUT;
    int t  = r / COUT;
    int ci = t % CINP;
    int k9 = t / CINP;
    float v = (ci < CIN) ? src[((size_t)(co*CIN + ci))*9 + k9] : 0.f;
    wp[idx] = __uint_as_float(f2tf(v));
}

// ---------------- tf32 tensor-core 3x3 conv --------------------------------
// CTA = 256 threads, computes 128-pixel row strip x COUT channels.
#define KC 16
#define PWD 136   // padded smem row width (136 % 32 == 8 -> conflict-free)

template<int COUT, int CIN, int DIL>
__global__ __launch_bounds__(256)
void conv_mma(const float* __restrict__ in, int CinS, int cinOff,
              const float* __restrict__ wp, const float* __restrict__ bias,
              float* __restrict__ out, int CoutS, int coutOff)
{
    constexpr int WM = (COUT >= 32) ? 32 : COUT;
    constexpr int NMW = COUT / WM;
    constexpr int NNW = 8 / NMW;
    constexpr int WN  = 128 / NNW;
    constexpr int MTILES = WM / 16;
    constexpr int NTILES = WN / 8;
    constexpr int CP  = COUT + 8;
    constexpr int HSH = (DIL==1) ? 1 : (DIL==2) ? 2 : 3;   // log2(2*DIL)
    constexpr int NHALO = 3*KC*2*DIL;                      // halo elements

    extern __shared__ __align__(16) unsigned smem_u[];
    unsigned* s_in = smem_u;                    // [3][KC][PWD]
    unsigned* s_w  = smem_u + 3*KC*PWD;         // [9][KC][CP]

    const int tid = threadIdx.x;
    const int x0  = blockIdx.x * 128;
    const int y   = blockIdx.y;
    const int bz  = blockIdx.z;
    const int wid = tid >> 5, lane = tid & 31;
    const int g = lane >> 2, c = lane & 3;
    const int wm = wid % NMW, wn = wid / NMW;

    float acc[MTILES][NTILES][4];
#pragma unroll
    for (int mt=0; mt<MTILES; mt++)
#pragma unroll
        for (int nt=0; nt<NTILES; nt++)
#pragma unroll
            for (int r=0; r<4; r++) acc[mt][nt][r] = 0.f;

#pragma unroll 1
    for (int ci0 = 0; ci0 < CIN; ci0 += KC) {
        __syncthreads();
        // async weight prefetch [9][KC][CP] (pure copy; already tf32 in gmem)
        {
            constexpr int NW4 = 9*KC*(COUT/4);
            const float4* wp4base = (const float4*)wp;
            for (int idx = tid; idx < NW4; idx += 256) {
                int co4 = idx % (COUT/4);
                int t   = idx / (COUT/4);
                int ci  = t % KC;
                int k9  = t / KC;
                unsigned dst = smem_u32((float*)s_w + (k9*KC + ci)*CP + co4*4);
                cpasync16(dst, wp4base + ((size_t)(k9*CIN + ci0 + ci))*(COUT/4) + co4);
            }
            asm volatile("cp.async.commit_group;");
        }
        // ---- input fill, main region: 48 rows x 128 px, shifts/masks only ----
        {
            const float* ibase = in + ((size_t)(bz*CinS + cinOff + ci0))*HWSZ;
            const int pxm = tid & 127;            // gx = x0 + pxm, always in-image
            const int r0  = tid >> 7;             // 0/1
#pragma unroll
            for (int it = 0; it < 24; it++) {
                const int rowIdx = it*2 + r0;     // 0..47
                const int row = rowIdx >> 4;      // 0..2
                const int ci  = rowIdx & 15;
                const int gy  = y + (row-1)*DIL;
                float v = 0.f;
                if ((unsigned)gy < HH)
                    v = ibase[(size_t)ci*HWSZ + (size_t)gy*WW + x0 + pxm];
                s_in[(rowIdx)*PWD + DIL + pxm] = f2tf(v);
            }
            // ---- halo: 48 rows x 2*DIL px ----
            for (int idx = tid; idx < NHALO; idx += 256) {
                const int off    = idx & (2*DIL - 1);
                const int rowIdx = idx >> HSH;
                const int row = rowIdx >> 4;
                const int ci  = rowIdx & 15;
                const int px  = (off < DIL) ? off : (128 + off);
                const int gy  = y + (row-1)*DIL;
                const int gx  = x0 - DIL + px;
                float v = 0.f;
                if ((unsigned)gy < HH && (unsigned)gx < WW)
                    v = ibase[(size_t)ci*HWSZ + (size_t)gy*WW + gx];
                s_in[(rowIdx)*PWD + px] = f2tf(v);
            }
        }
        asm volatile("cp.async.wait_group 0;" ::: "memory");
        __syncthreads();

#pragma unroll
        for (int ky=0; ky<3; ky++) {
#pragma unroll
            for (int kx=0; kx<3; kx++) {
                const int xoff = kx*DIL + wn*WN;
#pragma unroll
                for (int ks=0; ks<KC/8; ks++) {
                    unsigned a[MTILES][4];
#pragma unroll
                    for (int mt=0; mt<MTILES; mt++) {
                        const unsigned* wb = s_w + ((ky*3+kx)*KC + ks*8 + c)*CP + wm*WM + mt*16 + g;
                        a[mt][0] = wb[0];
                        a[mt][1] = wb[8];
                        a[mt][2] = wb[4*CP];
                        a[mt][3] = wb[4*CP + 8];
                    }
#pragma unroll
                    for (int nt=0; nt<NTILES; nt++) {
                        const unsigned* bb = s_in + (ky*KC + ks*8 + c)*PWD + xoff + nt*8 + g;
                        unsigned bv[2];
                        bv[0] = bb[0];
                        bv[1] = bb[4*PWD];
#pragma unroll
                        for (int mt=0; mt<MTILES; mt++)
                            mma8(acc[mt][nt], a[mt], bv);
                    }
                }
            }
        }
    }

    // epilogue -> NCHW
#pragma unroll
    for (int mt=0; mt<MTILES; mt++) {
        const int co0 = wm*WM + mt*16 + g;
        const float b0v = bias ? bias[co0]     : 0.f;
        const float b1v = bias ? bias[co0 + 8] : 0.f;
        float* o0 = out + ((size_t)(bz*CoutS + coutOff + co0))*HWSZ + (size_t)y*WW + x0 + wn*WN;
        float* o1 = o0 + (size_t)8*HWSZ;
#pragma unroll
        for (int nt=0; nt<NTILES; nt++) {
            const int px = nt*8 + 2*c;
            float2 v0; v0.x = acc[mt][nt][0] + b0v; v0.y = acc[mt][nt][1] + b0v;
            float2 v1; v1.x = acc[mt][nt][2] + b1v; v1.y = acc[mt][nt][3] + b1v;
            *(float2*)(o0 + px) = v0;
            *(float2*)(o1 + px) = v1;
        }
    }
}

// ---------------- tiny FFMA2 conv for the 16->2 head -----------------------
#define C_NT 128
#define C_TH 16
#define C_TW 64
#define C_CO 8

template<int DIL>
__global__ __launch_bounds__(C_NT, 3)
void conv3x3_kernel(const float* __restrict__ in, int Cin, int CinS, int cinOff,
                    const float* __restrict__ wgt, const float* __restrict__ bias,
                    float* __restrict__ out, int Cout, int CoutS, int coutOff)
{
    constexpr int TLW = C_TW + 2*DIL;
    constexpr int TLH = C_TH + 2*DIL;
    constexpr int NE  = (DIL==1) ? 5 : (DIL==2) ? 6 : 8;
    __shared__ __align__(16) float s_in[2][TLH*TLW];
    __shared__ __align__(16) ull   s_w2[2][C_CO*9];

    const int cb   = blockIdx.x * C_CO;
    const int tile = blockIdx.y;
    const int x0g  = (tile & 3) * C_TW;
    const int y0g  = (tile >> 2) * C_TH;
    const int b    = blockIdx.z;
    const int tid  = threadIdx.x;
    const int ty   = tid >> 3;
    const int xo   = (tid & 7) * 8;

    ull acc[C_CO][4];
#pragma unroll
    for (int co=0;co<C_CO;co++)
#pragma unroll
        for (int p=0;p<4;p++) acc[co][p] = 0ull;

    for (int ci0 = 0; ci0 < Cin; ci0 += 2) {
#pragma unroll
        for (int cc = 0; cc < 2; cc++) {
            const int ci = ci0 + cc;
            const float* ip = in + ((size_t)(b*CinS + cinOff + ci))*HWSZ;
            const bool cv = (ci < Cin);
            for (int idx = tid; idx < TLH*TLW; idx += C_NT) {
                int r = idx / TLW, cx = idx - r*TLW;
                int gy = y0g + r - DIL, gx = x0g + cx - DIL;
                float v = 0.f;
                if (cv && gy >= 0 && gy < HH && gx >= 0 && gx < WW) v = ip[gy*WW + gx];
                s_in[cc][idx] = v;
            }
        }
        for (int idx = tid; idx < 2*C_CO*9; idx += C_NT) {
            int cc = idx / (C_CO*9);
            int t  = idx - cc*(C_CO*9);
            int co = t / 9, k = t - co*9;
            int gci = ci0 + cc, gco = cb + co;
            float w = (gci < Cin && gco < Cout) ? wgt[((size_t)gco*Cin + gci)*9 + k] : 0.f;
            s_w2[cc][t] = pk2(w, w);
        }
        __syncthreads();
#pragma unroll
        for (int cc = 0; cc < 2; cc++) {
#pragma unroll
            for (int ky = 0; ky < 3; ky++) {
                const float* rowp = &s_in[cc][(ty + ky*DIL)*TLW + xo];
                ull E[NE];
#pragma unroll
                for (int i = 0; i < NE; i++) E[i] = *(const ull*)(rowp + 2*i);
                ull O[4];
                if (DIL == 1) {
#pragma unroll
                    for (int i = 0; i < 4; i++) O[i] = pk2(rowp[2*i+1], rowp[2*i+2]);
                }
#pragma unroll
                for (int kx = 0; kx < 3; kx++) {
                    ull vv[4];
                    if (DIL == 1) {
                        if (kx == 0)      { vv[0]=E[0]; vv[1]=E[1]; vv[2]=E[2]; vv[3]=E[3]; }
                        else if (kx == 1) { vv[0]=O[0]; vv[1]=O[1]; vv[2]=O[2]; vv[3]=O[3]; }
                        else              { vv[0]=E[1]; vv[1]=E[2]; vv[2]=E[3]; vv[3]=E[4]; }
                    } else {
                        const int base = kx*(DIL/2);
#pragma unroll
                        for (int p = 0; p < 4; p++) vv[p] = E[base + p];
                    }
#pragma unroll
                    for (int co = 0; co < C_CO; co++) {
                        ull w = s_w2[cc][co*9 + ky*3 + kx];
#pragma unroll
                        for (int p = 0; p < 4; p++) fma2(acc[co][p], w, vv[p]);
                    }
                }
            }
        }
        __syncthreads();
    }
#pragma unroll
    for (int co = 0; co < C_CO; co++) {
        int gco = cb + co;
        if (gco >= Cout) break;
        float bv = bias ? bias[gco] : 0.f;
        ull bv2 = pk2(bv, bv);
        float* op = out + ((size_t)(b*CoutS + coutOff + gco))*HWSZ + (y0g + ty)*WW + x0g + xo;
#pragma unroll
        for (int p = 0; p < 4; p++) {
            ull r = add2(acc[co][p], bv2);
            *(ull*)(op + 2*p) = r;
        }
    }
}

// ---------------- instance norm + leaky relu (in place, float4) ----------
__global__ void instnorm_lrelu_kernel(float* __restrict__ x, const float* __restrict__ gamma,
                                      const float* __restrict__ beta, int C)
{
    const int bc = blockIdx.x;
    float4* p = (float4*)(x + (size_t)bc*HWSZ);
    const int N4 = HWSZ/4;
    const int tid = threadIdx.x;
    float s = 0.f, s2 = 0.f;
    for (int i = tid; i < N4; i += 256) {
        float4 v = p[i];
        s  += v.x + v.y + v.z + v.w;
        s2 += v.x*v.x + v.y*v.y + v.z*v.z + v.w*v.w;
    }
    __shared__ float rs[256], rq[256];
    rs[tid] = s; rq[tid] = s2; __syncthreads();
    for (int off = 128; off > 0; off >>= 1) {
        if (tid < off) { rs[tid] += rs[tid+off]; rq[tid] += rq[tid+off]; }
        __syncthreads();
    }
    const float mu  = rs[0]*(1.f/HWSZ);
    const float var = rq[0]*(1.f/HWSZ) - mu*mu;
    const float inv = rsqrtf(var + 1e-5f);
    const int c = bc % C;
    const float ga = gamma[c]*inv, be = beta[c];
    for (int i = tid; i < N4; i += 256) {
        float4 v = p[i];
        v.x = (v.x-mu)*ga + be; v.x = (v.x >= 0.f) ? v.x : 0.2f*v.x;
        v.y = (v.y-mu)*ga + be; v.y = (v.y >= 0.f) ? v.y : 0.2f*v.y;
        v.z = (v.z-mu)*ga + be; v.z = (v.z >= 0.f) ? v.z : 0.2f*v.z;
        v.w = (v.w-mu)*ga + be; v.w = (v.w >= 0.f) ? v.w : 0.2f*v.w;
        p[i] = v;
    }
}

// ---------------- separable gaussian blur, replicate padding ------------
__global__ void blur_h_kernel(const float* __restrict__ in, int CinS, int cinOff,
                              float* __restrict__ out, int C, int n)
{
    int idx = blockIdx.x*blockDim.x + threadIdx.x;
    if (idx >= n) return;
    int x = idx % WW;
    int y = (idx / WW) % HH;
    int bc = idx / HWSZ;
    int b = bc / C, c = bc % C;
    const float* ip = in + ((size_t)(b*CinS + cinOff + c))*HWSZ + y*WW;
    float s = 0.f;
#pragma unroll
    for (int t = 0; t < 7; t++) {
        int xx = x + t - 3;
        xx = min(max(xx, 0), WW-1);
        s += GK[t]*ip[xx];
    }
    out[(size_t)bc*HWSZ + y*WW + x] = s;
}

__global__ void blur_v_kernel(const float* __restrict__ in, float* __restrict__ out, int n)
{
    int idx = blockIdx.x*blockDim.x + threadIdx.x;
    if (idx >= n) return;
    int x = idx % WW;
    int y = (idx / WW) % HH;
    int bc = idx / HWSZ;
    const float* ip = in + (size_t)bc*HWSZ;
    float s = 0.f;
#pragma unroll
    for (int t = 0; t < 7; t++) {
        int yy = y + t - 3;
        yy = min(max(yy, 0), HH-1);
        s += GK[t]*ip[yy*WW + x];
    }
    out[(size_t)bc*HWSZ + y*WW + x] = s;
}

// ---------------- local correlation ----------------
__global__ void corr_kernel(const float* __restrict__ f1s, const float* __restrict__ f2base,
                            float* __restrict__ out, float* __restrict__ lcsum)
{
    __shared__ float s1[22*22];
    __shared__ float red[256];
    const int bx = blockIdx.x, by = blockIdx.y, b = blockIdx.z;
    const int tid = threadIdx.x;
    const int ty = tid >> 4, tx = tid & 15;
    const int gy = by*16 + ty, gx = bx*16 + tx;

    float acc[49];
#pragma unroll
    for (int k = 0; k < 49; k++) acc[k] = 0.f;

    for (int c = 0; c < 64; c++) {
        const float* p1 = f1s    + ((size_t)(b*64  + c))*HWSZ;
        const float* p2 = f2base + ((size_t)(b*128 + 64 + c))*HWSZ;
        for (int idx = tid; idx < 22*22; idx += 256) {
            int r = idx/22, cc = idx%22;
            int yy = by*16 + r - 3, xx = bx*16 + cc - 3;
            s1[idx] = (yy >= 0 && yy < HH && xx >= 0 && xx < WW) ? p1[yy*WW+xx] : 0.f;
        }
        __syncthreads();
        const float v2 = p2[gy*WW + gx];
#pragma unroll
        for (int i = 0; i < 7; i++) {
#pragma unroll
            for (int j = 0; j < 7; j++) {
                float d = v2 - s1[(ty+i)*22 + tx+j];
                acc[i*7+j] += d*d;
            }
        }
        __syncthreads();
    }
    float tsum = 0.f;
#pragma unroll
    for (int k = 0; k < 49; k++) {
        float lc = acc[k]*(1.f/64.f);
        out[((size_t)(b*128 + 64 + k))*HWSZ + gy*WW + gx] = lc;
        tsum += lc;
    }
    red[tid] = tsum; __syncthreads();
    for (int off = 128; off > 0; off >>= 1) {
        if (tid < off) red[tid] += red[tid+off];
        __syncthreads();
    }
    if (tid == 0) atomicAdd(&lcsum[b], red[0]);
}

__global__ void zero_lcsum_kernel(float* lcsum)
{
    if (threadIdx.x < BB) lcsum[threadIdx.x] = 0.f;
}

__global__ void lcnorm_kernel(float* __restrict__ corr, const float* __restrict__ lcsum, int n)
{
    int idx = blockIdx.x*blockDim.x + threadIdx.x;
    if (idx >= n) return;
    int b = idx / (49*HWSZ);
    int r = idx - b*(49*HWSZ);
    float mean = lcsum[b]*(1.f/(49.f*HWSZ));
    float s = 1.f/(mean + 1e-6f);
    corr[((size_t)b*128 + 64)*HWSZ + r] *= s;
}

// ---------------- host side ----------------
template<int COUT, int CIN, int DIL>
static void launch_mma(const float* in, int CinS, int cinOff,
                       const float* wp, const float* bias,
                       float* out, int CoutS, int coutOff)
{
    const int smem = (3*KC*PWD + 9*KC*(COUT+8))*4;
    cudaFuncSetAttribute(conv_mma<COUT,CIN,DIL>,
                         cudaFuncAttributeMaxDynamicSharedMemorySize, smem);
    conv_mma<COUT,CIN,DIL><<<dim3(2, HH, BB), 256, smem>>>(
        in, CinS, cinOff, wp, bias, out, CoutS, coutOff);
}

extern "C" void kernel_launch(void* const* d_in, const int* in_sizes, int n_in,
                              void* d_out, int out_size)
{
    const float* feat1  = (const float*)d_in[0];
    const float* feat2  = (const float*)d_in[1];
    const float* pre_w  = (const float*)d_in[2];
    const float* pre_b  = (const float*)d_in[3];
    const float* fc1_w  = (const float*)d_in[4];
    const float* fc1_g  = (const float*)d_in[5];
    const float* fc1_be = (const float*)d_in[6];
    const float* fc2_w  = (const float*)d_in[7];
    const float* fc2_b  = (const float*)d_in[8];
    const float* e1_w   = (const float*)d_in[9];
    const float* e1_g   = (const float*)d_in[10];
    const float* e1_be  = (const float*)d_in[11];
    const float* e2_w   = (const float*)d_in[12];
    const float* e2_g   = (const float*)d_in[13];
    const float* e2_be  = (const float*)d_in[14];
    const float* e3_w   = (const float*)d_in[15];
    const float* e3_g   = (const float*)d_in[16];
    const float* e3_be  = (const float*)d_in[17];
    const float* head_w = (const float*)d_in[18];
    const float* head_b = (const float*)d_in[19];
    float* out = (float*)d_out;

    float *cat_, *x128, *corr_, *f1s, *tmp_, *x64, *x32, *x16, *head_, *lcsum, *wpb;
    cudaGetSymbolAddress((void**)&cat_,  g_cat);
    cudaGetSymbolAddress((void**)&x128,  g_x128);
    cudaGetSymbolAddress((void**)&corr_, g_corr);
    cudaGetSymbolAddress((void**)&f1s,   g_f1s);
    cudaGetSymbolAddress((void**)&tmp_,  g_tmp);
    cudaGetSymbolAddress((void**)&x64,   g_x64);
    cudaGetSymbolAddress((void**)&x32,   g_x32);
    cudaGetSymbolAddress((void**)&x16,   g_x16);
    cudaGetSymbolAddress((void**)&head_, g_head);
    cudaGetSymbolAddress((void**)&lcsum, g_lcsum);
    cudaGetSymbolAddress((void**)&wpb,   g_wp);

    float* wp_pre = wpb;
    float* wp_fc1 = wpb + 36864;
    float* wp_fc2 = wpb + 184320;
    float* wp_e1  = wpb + 258048;
    float* wp_e2  = wpb + 331776;
    float* wp_e3  = wpb + 350208;

    // single merged weight prep (reorder + tf32 round + ci pad)
    prep_all_kernel<<<(354816 + 255)/256, 256>>>(pre_w, fc1_w, fc2_w, e1_w, e2_w, e3_w, wpb);

    // preprocessor (shared weights) -> concat buffer
    launch_mma<64,64,1>(feat1, 64, 0, wp_pre, pre_b, cat_, 128, 0);
    launch_mma<64,64,1>(feat2, 64, 0, wp_pre, pre_b, cat_, 128, 64);

    // featcompressor layer1 + IN + lrelu
    launch_mma<128,128,1>(cat_, 128, 0, wp_fc1, nullptr, x128, 128, 0);
    instnorm_lrelu_kernel<<<BB*128, 256>>>(x128, fc1_g, fc1_be, 128);

    // featcompressor layer2 -> corr channels 0..63
    launch_mma<64,128,1>(x128, 128, 0, wp_fc2, fc2_b, corr_, 128, 0);

    // gaussian blur of f1 (replicate pad, separable)
    {
        int n = BB*64*HWSZ;
        blur_h_kernel<<<(n+255)/256, 256>>>(cat_, 128, 0, tmp_, 64, n);
        blur_v_kernel<<<(n+255)/256, 256>>>(tmp_, f1s, n);
    }

    // local correlation -> corr channels 64..112, then normalize by batch mean
    zero_lcsum_kernel<<<1, 32>>>(lcsum);
    corr_kernel<<<dim3(WW/16, HH/16, BB), 256>>>(f1s, cat_, corr_, lcsum);
    {
        int n = BB*49*HWSZ;
        lcnorm_kernel<<<(n+255)/256, 256>>>(corr_, lcsum, n);
    }

    // estimator stack (e1 reads 128-ch corr; weights zero-padded for ci>=113)
    launch_mma<64,128,1>(corr_, 128, 0, wp_e1, nullptr, x64, 64, 0);
    instnorm_lrelu_kernel<<<BB*64, 256>>>(x64, e1_g, e1_be, 64);

    launch_mma<32,64,2>(x64, 64, 0, wp_e2, nullptr, x32, 32, 0);
    instnorm_lrelu_kernel<<<BB*32, 256>>>(x32, e2_g, e2_be, 32);

    launch_mma<16,32,4>(x32, 32, 0, wp_e3, nullptr, x16, 16, 0);
    instnorm_lrelu_kernel<<<BB*16, 256>>>(x16, e3_g, e3_be, 16);

    // flow head (tiny, FFMA2 direct conv)
    {
        dim3 grid(1, (WW/C_TW)*(HH/C_TH), BB);
        conv3x3_kernel<1><<<grid, C_NT>>>(x16, 16, 16, 0, head_w, head_b, head_, 2, 2, 0);
    }

    // final blur -> output
    {
        int n = BB*2*HWSZ;
        blur_h_kernel<<<(n+255)/256, 256>>>(head_, 2, 0, tmp_, 2, n);
        blur_v_kernel<<<(n+255)/256, 256>>>(tmp_, out, n);
    }
}

// round 8
// speedup vs baseline: 1.4585x; 1.0463x over previous
#include <cuda_runtime.h>
#include <math.h>

// ---------------- problem constants ----------------
#define BB 4
#define HH 256
#define WW 256
#define HWSZ (HH*WW)

typedef unsigned long long ull;

// ---------------- scratch buffers ----------------
__device__ float g_cat   [(size_t)BB*128*HWSZ]; // raw f1|f2 (for blur/corr)
__device__ float g_cattf [(size_t)BB*128*HWSZ]; // tf32-rounded f1|f2 (for fc1)
__device__ float g_ftf   [(size_t)BB*128*HWSZ]; // tf32-rounded feat1|feat2 (for pre)
__device__ float g_x128  [(size_t)BB*128*HWSZ]; // fc1 out (raw), instnorm rounds in place
__device__ float g_corr  [(size_t)BB*128*HWSZ]; // feat(0..63,rounded) | lc(64..112,rounded) | 0
__device__ float g_f1s   [(size_t)BB*64*HWSZ];
__device__ float g_tmp   [(size_t)BB*64*HWSZ];
__device__ float g_x64   [(size_t)BB*64*HWSZ];
__device__ float g_x32   [(size_t)BB*32*HWSZ];
__device__ float g_x16   [(size_t)BB*16*HWSZ];
__device__ float g_head  [(size_t)BB*2*HWSZ];
__device__ float g_lcsum[BB];
__device__ float g_wp[36864 + 147456 + 73728 + 73728 + 18432 + 4608];

__constant__ float GK[7] = {0.03663285f, 0.11128102f, 0.21674443f, 0.27068263f,
                            0.21674443f, 0.11128102f, 0.03663285f};

// ---------------- helpers ----------------
__device__ __forceinline__ unsigned f2tf(float f) {
    unsigned r; asm("cvt.rna.tf32.f32 %0, %1;" : "=r"(r) : "f"(f)); return r;
}
__device__ __forceinline__ float rndtf(float f) { return __uint_as_float(f2tf(f)); }
__device__ __forceinline__ void mma8(float* d, const unsigned* a, const unsigned* b) {
    asm volatile("mma.sync.aligned.m16n8k8.row.col.f32.tf32.tf32.f32 "
        "{%0,%1,%2,%3}, {%4,%5,%6,%7}, {%8,%9}, {%0,%1,%2,%3};\n"
        : "+f"(d[0]), "+f"(d[1]), "+f"(d[2]), "+f"(d[3])
        : "r"(a[0]), "r"(a[1]), "r"(a[2]), "r"(a[3]), "r"(b[0]), "r"(b[1]));
}
__device__ __forceinline__ ull pk2(float lo, float hi) {
    ull r; asm("mov.b64 %0, {%1, %2};" : "=l"(r) : "f"(lo), "f"(hi)); return r;
}
__device__ __forceinline__ void fma2(ull& d, ull a, ull b) {
    asm("fma.rn.f32x2 %0, %1, %2, %0;" : "+l"(d) : "l"(a), "l"(b));
}
__device__ __forceinline__ ull add2(ull a, ull b) {
    ull r; asm("add.rn.f32x2 %0, %1, %2;" : "=l"(r) : "l"(a), "l"(b)); return r;
}
__device__ __forceinline__ unsigned smem_u32(const void* p) {
    return (unsigned)__cvta_generic_to_shared(p);
}
__device__ __forceinline__ void cpasync16(unsigned dst, const void* src) {
    asm volatile("cp.async.cg.shared.global [%0], [%1], 16;" :: "r"(dst), "l"(src));
}
__device__ __forceinline__ void cpasync16_z(unsigned dst, const void* src) {
    asm volatile("cp.async.cg.shared.global [%0], [%1], 16, 0;" :: "r"(dst), "l"(src));
}

// ---------------- merged weight prep ---------------------------------------
__global__ void prep_all_kernel(const float* __restrict__ w_pre,
                                const float* __restrict__ w_fc1,
                                const float* __restrict__ w_fc2,
                                const float* __restrict__ w_e1,
                                const float* __restrict__ w_e2,
                                const float* __restrict__ w_e3,
                                float* __restrict__ wp)
{
    int idx = blockIdx.x*256 + threadIdx.x;
    const float* src; int COUT, CIN, CINP, r;
    if      (idx < 36864)  { src=w_pre; COUT=64;  CIN=64;  CINP=64;  r=idx; }
    else if (idx < 184320) { src=w_fc1; COUT=128; CIN=128; CINP=128; r=idx-36864; }
    else if (idx < 258048) { src=w_fc2; COUT=64;  CIN=128; CINP=128; r=idx-184320; }
    else if (idx < 331776) { src=w_e1;  COUT=64;  CIN=113; CINP=128; r=idx-258048; }
    else if (idx < 350208) { src=w_e2;  COUT=32;  CIN=64;  CINP=64;  r=idx-331776; }
    else if (idx < 354816) { src=w_e3;  COUT=16;  CIN=32;  CINP=32;  r=idx-350208; }
    else return;
    int co = r % COUT;
    int t  = r / COUT;
    int ci = t % CINP;
    int k9 = t / CINP;
    float v = (ci < CIN) ? src[((size_t)(co*CIN + ci))*9 + k9] : 0.f;
    wp[idx] = rndtf(v);
}

// ---------------- feat round prep: feat1|feat2 -> g_ftf (tf32) -------------
__global__ void prep_feat_kernel(const float4* __restrict__ f1,
                                 const float4* __restrict__ f2,
                                 float4* __restrict__ dst)
{
    const int n4 = BB*64*HWSZ/4;
    int i = blockIdx.x*256 + threadIdx.x;
    if (i >= 2*n4) return;
    float4 v = (i < n4) ? f1[i] : f2[i - n4];
    v.x = rndtf(v.x); v.y = rndtf(v.y); v.z = rndtf(v.z); v.w = rndtf(v.w);
    dst[i] = v;
}

// ---------------- tf32 tensor-core 3x3 conv --------------------------------
// CTA = 256 threads, 128-pixel row strip x COUT channels. Inputs in gmem are
// ALREADY tf32-rounded -> fill is pure cp.async copy.
// smem row layout: [pad | left halo | main(128 @ float-offset 4) | right halo]
#define KC 16
#define PWD 136

// WMODE: 0 = raw out; 1 = rounded out; 2 = raw out + rounded out2
template<int COUT, int CIN, int DIL, int WMODE>
__global__ __launch_bounds__(256)
void conv_mma(const float* __restrict__ in, int CinS, int cinOff,
              const float* __restrict__ wp, const float* __restrict__ bias,
              float* __restrict__ out, int CoutS, int coutOff,
              float* __restrict__ out2)
{
    constexpr int WM = (COUT >= 32) ? 32 : COUT;
    constexpr int NMW = COUT / WM;
    constexpr int NNW = 8 / NMW;
    constexpr int WN  = 128 / NNW;
    constexpr int MTILES = WM / 16;
    constexpr int NTILES = WN / 8;
    constexpr int CP  = COUT + 8;
    constexpr int HSH = (DIL==1) ? 1 : (DIL==2) ? 2 : 3;
    constexpr int NHALO = 3*KC*2*DIL;
    constexpr int MBASE = 4 - DIL;   // smem float-offset of img px (x0 - DIL)

    extern __shared__ __align__(16) unsigned smem_u[];
    unsigned* s_in = smem_u;                    // [3*KC][PWD]
    unsigned* s_w  = smem_u + 3*KC*PWD;         // [9][KC][CP]

    const int tid = threadIdx.x;
    const int x0  = blockIdx.x * 128;
    const int y   = blockIdx.y;
    const int bz  = blockIdx.z;
    const int wid = tid >> 5, lane = tid & 31;
    const int g = lane >> 2, c = lane & 3;
    const int wm = wid % NMW, wn = wid / NMW;

    float acc[MTILES][NTILES][4];
#pragma unroll
    for (int mt=0; mt<MTILES; mt++)
#pragma unroll
        for (int nt=0; nt<NTILES; nt++)
#pragma unroll
            for (int r=0; r<4; r++) acc[mt][nt][r] = 0.f;

#pragma unroll 1
    for (int ci0 = 0; ci0 < CIN; ci0 += KC) {
        __syncthreads();
        // weights [9][KC][CP] via cp.async (pure copy)
        {
            constexpr int NW4 = 9*KC*(COUT/4);
            const float4* wp4base = (const float4*)wp;
            for (int idx = tid; idx < NW4; idx += 256) {
                int co4 = idx % (COUT/4);
                int t   = idx / (COUT/4);
                int ci  = t % KC;
                int k9  = t / KC;
                unsigned dst = smem_u32((float*)s_w + (k9*KC + ci)*CP + co4*4);
                cpasync16(dst, wp4base + ((size_t)(k9*CIN + ci0 + ci))*(COUT/4) + co4);
            }
        }
        // input main region: 48 rows x 128 px = 1536 x 16B chunks, pure cp.async
        {
            const float* ibase = in + ((size_t)(bz*CinS + cinOff + ci0))*HWSZ;
#pragma unroll
            for (int it = 0; it < 6; it++) {
                const int idx    = tid + it*256;
                const int chunk  = idx & 31;          // 0..31 (16B units)
                const int rowIdx = idx >> 5;          // 0..47
                const int row = rowIdx >> 4;
                const int ci  = rowIdx & 15;
                const int gy  = y + (row-1)*DIL;
                unsigned dst = smem_u32((float*)s_in + rowIdx*PWD + 4 + chunk*4);
                const float* src = ibase + (size_t)ci*HWSZ
                                 + (size_t)min(max(gy,0),HH-1)*WW + x0 + chunk*4;
                if ((unsigned)gy < HH) cpasync16(dst, src);
                else                   cpasync16_z(dst, src);
            }
            asm volatile("cp.async.commit_group;");
            // halo: 48 rows x 2*DIL px, scalar (values already rounded)
            for (int idx = tid; idx < NHALO; idx += 256) {
                const int off    = idx & (2*DIL - 1);
                const int rowIdx = idx >> HSH;
                const int row = rowIdx >> 4;
                const int ci  = rowIdx & 15;
                const int px  = (off < DIL) ? (4 - DIL + off) : (132 + off - DIL);
                const int gx  = x0 + ((off < DIL) ? (off - DIL) : (128 + off - DIL));
                const int gy  = y + (row-1)*DIL;
                float v = 0.f;
                if ((unsigned)gy < HH && (unsigned)gx < WW)
                    v = ibase[(size_t)ci*HWSZ + (size_t)gy*WW + gx];
                ((float*)s_in)[rowIdx*PWD + px] = v;
            }
        }
        asm volatile("cp.async.wait_group 0;" ::: "memory");
        __syncthreads();

#pragma unroll
        for (int ky=0; ky<3; ky++) {
#pragma unroll
            for (int kx=0; kx<3; kx++) {
                const int xoff = MBASE + kx*DIL + wn*WN;
#pragma unroll
                for (int ks=0; ks<KC/8; ks++) {
                    unsigned a[MTILES][4];
#pragma unroll
                    for (int mt=0; mt<MTILES; mt++) {
                        const unsigned* wb = s_w + ((ky*3+kx)*KC + ks*8 + c)*CP + wm*WM + mt*16 + g;
                        a[mt][0] = wb[0];
                        a[mt][1] = wb[8];
                        a[mt][2] = wb[4*CP];
                        a[mt][3] = wb[4*CP + 8];
                    }
#pragma unroll
                    for (int nt=0; nt<NTILES; nt++) {
                        const unsigned* bb = s_in + (ky*KC + ks*8 + c)*PWD + xoff + nt*8 + g;
                        unsigned bv[2];
                        bv[0] = bb[0];
                        bv[1] = bb[4*PWD];
#pragma unroll
                        for (int mt=0; mt<MTILES; mt++)
                            mma8(acc[mt][nt], a[mt], bv);
                    }
                }
            }
        }
    }

    // epilogue -> NCHW
#pragma unroll
    for (int mt=0; mt<MTILES; mt++) {
        const int co0 = wm*WM + mt*16 + g;
        const float b0v = bias ? bias[co0]     : 0.f;
        const float b1v = bias ? bias[co0 + 8] : 0.f;
        const size_t obase = ((size_t)(bz*CoutS + coutOff + co0))*HWSZ + (size_t)y*WW + x0 + wn*WN;
        float* o0 = out + obase;
        float* o1 = o0 + (size_t)8*HWSZ;
#pragma unroll
        for (int nt=0; nt<NTILES; nt++) {
            const int px = nt*8 + 2*c;
            float2 v0, v1;
            v0.x = acc[mt][nt][0] + b0v; v0.y = acc[mt][nt][1] + b0v;
            v1.x = acc[mt][nt][2] + b1v; v1.y = acc[mt][nt][3] + b1v;
            if (WMODE == 1) {
                v0.x = rndtf(v0.x); v0.y = rndtf(v0.y);
                v1.x = rndtf(v1.x); v1.y = rndtf(v1.y);
            }
            *(float2*)(o0 + px) = v0;
            *(float2*)(o1 + px) = v1;
            if (WMODE == 2) {
                float2 r0, r1;
                r0.x = rndtf(v0.x); r0.y = rndtf(v0.y);
                r1.x = rndtf(v1.x); r1.y = rndtf(v1.y);
                *(float2*)(out2 + obase + px) = r0;
                *(float2*)(out2 + obase + (size_t)8*HWSZ + px) = r1;
            }
        }
    }
}

// ---------------- tiny FFMA2 conv for the 16->2 head -----------------------
#define C_NT 128
#define C_TH 16
#define C_TW 64
#define C_CO 8

template<int DIL>
__global__ __launch_bounds__(C_NT, 3)
void conv3x3_kernel(const float* __restrict__ in, int Cin, int CinS, int cinOff,
                    const float* __restrict__ wgt, const float* __restrict__ bias,
                    float* __restrict__ out, int Cout, int CoutS, int coutOff)
{
    constexpr int TLW = C_TW + 2*DIL;
    constexpr int TLH = C_TH + 2*DIL;
    constexpr int NE  = (DIL==1) ? 5 : (DIL==2) ? 6 : 8;
    __shared__ __align__(16) float s_in[2][TLH*TLW];
    __shared__ __align__(16) ull   s_w2[2][C_CO*9];

    const int cb   = blockIdx.x * C_CO;
    const int tile = blockIdx.y;
    const int x0g  = (tile & 3) * C_TW;
    const int y0g  = (tile >> 2) * C_TH;
    const int b    = blockIdx.z;
    const int tid  = threadIdx.x;
    const int ty   = tid >> 3;
    const int xo   = (tid & 7) * 8;

    ull acc[C_CO][4];
#pragma unroll
    for (int co=0;co<C_CO;co++)
#pragma unroll
        for (int p=0;p<4;p++) acc[co][p] = 0ull;

    for (int ci0 = 0; ci0 < Cin; ci0 += 2) {
#pragma unroll
        for (int cc = 0; cc < 2; cc++) {
            const int ci = ci0 + cc;
            const float* ip = in + ((size_t)(b*CinS + cinOff + ci))*HWSZ;
            const bool cv = (ci < Cin);
            for (int idx = tid; idx < TLH*TLW; idx += C_NT) {
                int r = idx / TLW, cx = idx - r*TLW;
                int gy = y0g + r - DIL, gx = x0g + cx - DIL;
                float v = 0.f;
                if (cv && gy >= 0 && gy < HH && gx >= 0 && gx < WW) v = ip[gy*WW + gx];
                s_in[cc][idx] = v;
            }
        }
        for (int idx = tid; idx < 2*C_CO*9; idx += C_NT) {
            int cc = idx / (C_CO*9);
            int t  = idx - cc*(C_CO*9);
            int co = t / 9, k = t - co*9;
            int gci = ci0 + cc, gco = cb + co;
            float w = (gci < Cin && gco < Cout) ? wgt[((size_t)gco*Cin + gci)*9 + k] : 0.f;
            s_w2[cc][t] = pk2(w, w);
        }
        __syncthreads();
#pragma unroll
        for (int cc = 0; cc < 2; cc++) {
#pragma unroll
            for (int ky = 0; ky < 3; ky++) {
                const float* rowp = &s_in[cc][(ty + ky*DIL)*TLW + xo];
                ull E[NE];
#pragma unroll
                for (int i = 0; i < NE; i++) E[i] = *(const ull*)(rowp + 2*i);
                ull O[4];
                if (DIL == 1) {
#pragma unroll
                    for (int i = 0; i < 4; i++) O[i] = pk2(rowp[2*i+1], rowp[2*i+2]);
                }
#pragma unroll
                for (int kx = 0; kx < 3; kx++) {
                    ull vv[4];
                    if (DIL == 1) {
                        if (kx == 0)      { vv[0]=E[0]; vv[1]=E[1]; vv[2]=E[2]; vv[3]=E[3]; }
                        else if (kx == 1) { vv[0]=O[0]; vv[1]=O[1]; vv[2]=O[2]; vv[3]=O[3]; }
                        else              { vv[0]=E[1]; vv[1]=E[2]; vv[2]=E[3]; vv[3]=E[4]; }
                    } else {
                        const int base = kx*(DIL/2);
#pragma unroll
                        for (int p = 0; p < 4; p++) vv[p] = E[base + p];
                    }
#pragma unroll
                    for (int co = 0; co < C_CO; co++) {
                        ull w = s_w2[cc][co*9 + ky*3 + kx];
#pragma unroll
                        for (int p = 0; p < 4; p++) fma2(acc[co][p], w, vv[p]);
                    }
                }
            }
        }
        __syncthreads();
    }
#pragma unroll
    for (int co = 0; co < C_CO; co++) {
        int gco = cb + co;
        if (gco >= Cout) break;
        float bv = bias ? bias[gco] : 0.f;
        ull bv2 = pk2(bv, bv);
        float* op = out + ((size_t)(b*CoutS + coutOff + gco))*HWSZ + (y0g + ty)*WW + x0g + xo;
#pragma unroll
        for (int p = 0; p < 4; p++) {
            ull r = add2(acc[co][p], bv2);
            *(ull*)(op + 2*p) = r;
        }
    }
}

// ---------------- instance norm + leaky relu (in place, float4) ----------
__global__ void instnorm_lrelu_kernel(float* __restrict__ x, const float* __restrict__ gamma,
                                      const float* __restrict__ beta, int C, int rnd)
{
    const int bc = blockIdx.x;
    float4* p = (float4*)(x + (size_t)bc*HWSZ);
    const int N4 = HWSZ/4;
    const int tid = threadIdx.x;
    float s = 0.f, s2 = 0.f;
    for (int i = tid; i < N4; i += 256) {
        float4 v = p[i];
        s  += v.x + v.y + v.z + v.w;
        s2 += v.x*v.x + v.y*v.y + v.z*v.z + v.w*v.w;
    }
    __shared__ float rs[256], rq[256];
    rs[tid] = s; rq[tid] = s2; __syncthreads();
    for (int off = 128; off > 0; off >>= 1) {
        if (tid < off) { rs[tid] += rs[tid+off]; rq[tid] += rq[tid+off]; }
        __syncthreads();
    }
    const float mu  = rs[0]*(1.f/HWSZ);
    const float var = rq[0]*(1.f/HWSZ) - mu*mu;
    const float inv = rsqrtf(var + 1e-5f);
    const int c = bc % C;
    const float ga = gamma[c]*inv, be = beta[c];
    for (int i = tid; i < N4; i += 256) {
        float4 v = p[i];
        v.x = (v.x-mu)*ga + be; v.x = (v.x >= 0.f) ? v.x : 0.2f*v.x;
        v.y = (v.y-mu)*ga + be; v.y = (v.y >= 0.f) ? v.y : 0.2f*v.y;
        v.z = (v.z-mu)*ga + be; v.z = (v.z >= 0.f) ? v.z : 0.2f*v.z;
        v.w = (v.w-mu)*ga + be; v.w = (v.w >= 0.f) ? v.w : 0.2f*v.w;
        if (rnd) {
            v.x = rndtf(v.x); v.y = rndtf(v.y); v.z = rndtf(v.z); v.w = rndtf(v.w);
        }
        p[i] = v;
    }
}

// ---------------- separable gaussian blur, replicate padding ------------
__global__ void blur_h_kernel(const float* __restrict__ in, int CinS, int cinOff,
                              float* __restrict__ out, int C, int n)
{
    int idx = blockIdx.x*blockDim.x + threadIdx.x;
    if (idx >= n) return;
    int x = idx % WW;
    int y = (idx / WW) % HH;
    int bc = idx / HWSZ;
    int b = bc / C, c = bc % C;
    const float* ip = in + ((size_t)(b*CinS + cinOff + c))*HWSZ + y*WW;
    float s = 0.f;
#pragma unroll
    for (int t = 0; t < 7; t++) {
        int xx = x + t - 3;
        xx = min(max(xx, 0), WW-1);
        s += GK[t]*ip[xx];
    }
    out[(size_t)bc*HWSZ + y*WW + x] = s;
}

__global__ void blur_v_kernel(const float* __restrict__ in, float* __restrict__ out, int n)
{
    int idx = blockIdx.x*blockDim.x + threadIdx.x;
    if (idx >= n) return;
    int x = idx % WW;
    int y = (idx / WW) % HH;
    int bc = idx / HWSZ;
    const float* ip = in + (size_t)bc*HWSZ;
    float s = 0.f;
#pragma unroll
    for (int t = 0; t < 7; t++) {
        int yy = y + t - 3;
        yy = min(max(yy, 0), HH-1);
        s += GK[t]*ip[yy*WW + x];
    }
    out[(size_t)bc*HWSZ + y*WW + x] = s;
}

// ---------------- local correlation ----------------
__global__ void corr_kernel(const float* __restrict__ f1s, const float* __restrict__ f2base,
                            float* __restrict__ out, float* __restrict__ lcsum)
{
    __shared__ float s1[22*22];
    __shared__ float red[256];
    const int bx = blockIdx.x, by = blockIdx.y, b = blockIdx.z;
    const int tid = threadIdx.x;
    const int ty = tid >> 4, tx = tid & 15;
    const int gy = by*16 + ty, gx = bx*16 + tx;

    float acc[49];
#pragma unroll
    for (int k = 0; k < 49; k++) acc[k] = 0.f;

    for (int c = 0; c < 64; c++) {
        const float* p1 = f1s    + ((size_t)(b*64  + c))*HWSZ;
        const float* p2 = f2base + ((size_t)(b*128 + 64 + c))*HWSZ;
        for (int idx = tid; idx < 22*22; idx += 256) {
            int r = idx/22, cc = idx%22;
            int yy = by*16 + r - 3, xx = bx*16 + cc - 3;
            s1[idx] = (yy >= 0 && yy < HH && xx >= 0 && xx < WW) ? p1[yy*WW+xx] : 0.f;
        }
        __syncthreads();
        const float v2 = p2[gy*WW + gx];
#pragma unroll
        for (int i = 0; i < 7; i++) {
#pragma unroll
            for (int j = 0; j < 7; j++) {
                float d = v2 - s1[(ty+i)*22 + tx+j];
                acc[i*7+j] += d*d;
            }
        }
        __syncthreads();
    }
    float tsum = 0.f;
#pragma unroll
    for (int k = 0; k < 49; k++) {
        float lc = acc[k]*(1.f/64.f);
        out[((size_t)(b*128 + 64 + k))*HWSZ + gy*WW + gx] = lc;
        tsum += lc;
    }
    red[tid] = tsum; __syncthreads();
    for (int off = 128; off > 0; off >>= 1) {
        if (tid < off) red[tid] += red[tid+off];
        __syncthreads();
    }
    if (tid == 0) atomicAdd(&lcsum[b], red[0]);
}

__global__ void zero_lcsum_kernel(float* lcsum)
{
    if (threadIdx.x < BB) lcsum[threadIdx.x] = 0.f;
}

__global__ void lcnorm_kernel(float* __restrict__ corr, const float* __restrict__ lcsum, int n)
{
    int idx = blockIdx.x*blockDim.x + threadIdx.x;
    if (idx >= n) return;
    int b = idx / (49*HWSZ);
    int r = idx - b*(49*HWSZ);
    float mean = lcsum[b]*(1.f/(49.f*HWSZ));
    float s = 1.f/(mean + 1e-6f);
    float* p = &corr[((size_t)b*128 + 64)*HWSZ + r];
    *p = rndtf(*p * s);
}

// ---------------- host side ----------------
template<int COUT, int CIN, int DIL, int WMODE>
static void launch_mma(const float* in, int CinS, int cinOff,
                       const float* wp, const float* bias,
                       float* out, int CoutS, int coutOff, float* out2)
{
    const int smem = (3*KC*PWD + 9*KC*(COUT+8))*4;
    cudaFuncSetAttribute(conv_mma<COUT,CIN,DIL,WMODE>,
                         cudaFuncAttributeMaxDynamicSharedMemorySize, smem);
    conv_mma<COUT,CIN,DIL,WMODE><<<dim3(2, HH, BB), 256, smem>>>(
        in, CinS, cinOff, wp, bias, out, CoutS, coutOff, out2);
}

extern "C" void kernel_launch(void* const* d_in, const int* in_sizes, int n_in,
                              void* d_out, int out_size)
{
    const float* feat1  = (const float*)d_in[0];
    const float* feat2  = (const float*)d_in[1];
    const float* pre_w  = (const float*)d_in[2];
    const float* pre_b  = (const float*)d_in[3];
    const float* fc1_w  = (const float*)d_in[4];
    const float* fc1_g  = (const float*)d_in[5];
    const float* fc1_be = (const float*)d_in[6];
    const float* fc2_w  = (const float*)d_in[7];
    const float* fc2_b  = (const float*)d_in[8];
    const float* e1_w   = (const float*)d_in[9];
    const float* e1_g   = (const float*)d_in[10];
    const float* e1_be  = (const float*)d_in[11];
    const float* e2_w   = (const float*)d_in[12];
    const float* e2_g   = (const float*)d_in[13];
    const float* e2_be  = (const float*)d_in[14];
    const float* e3_w   = (const float*)d_in[15];
    const float* e3_g   = (const float*)d_in[16];
    const float* e3_be  = (const float*)d_in[17];
    const float* head_w = (const float*)d_in[18];
    const float* head_b = (const float*)d_in[19];
    float* out = (float*)d_out;

    float *cat_, *cattf, *ftf, *x128, *corr_, *f1s, *tmp_, *x64, *x32, *x16, *head_, *lcsum, *wpb;
    cudaGetSymbolAddress((void**)&cat_,  g_cat);
    cudaGetSymbolAddress((void**)&cattf, g_cattf);
    cudaGetSymbolAddress((void**)&ftf,   g_ftf);
    cudaGetSymbolAddress((void**)&x128,  g_x128);
    cudaGetSymbolAddress((void**)&corr_, g_corr);
    cudaGetSymbolAddress((void**)&f1s,   g_f1s);
    cudaGetSymbolAddress((void**)&tmp_,  g_tmp);
    cudaGetSymbolAddress((void**)&x64,   g_x64);
    cudaGetSymbolAddress((void**)&x32,   g_x32);
    cudaGetSymbolAddress((void**)&x16,   g_x16);
    cudaGetSymbolAddress((void**)&head_, g_head);
    cudaGetSymbolAddress((void**)&lcsum, g_lcsum);
    cudaGetSymbolAddress((void**)&wpb,   g_wp);

    float* wp_pre = wpb;
    float* wp_fc1 = wpb + 36864;
    float* wp_fc2 = wpb + 184320;
    float* wp_e1  = wpb + 258048;
    float* wp_e2  = wpb + 331776;
    float* wp_e3  = wpb + 350208;

    // weight prep + feat rounding
    prep_all_kernel<<<(354816 + 255)/256, 256>>>(pre_w, fc1_w, fc2_w, e1_w, e2_w, e3_w, wpb);
    prep_feat_kernel<<<(2*(BB*64*HWSZ/4) + 255)/256, 256>>>(
        (const float4*)feat1, (const float4*)feat2, (float4*)ftf);

    // preprocessor -> cat (raw, for blur/corr) + cattf (rounded, for fc1)
    launch_mma<64,64,1,2>(ftf, 64, 0, wp_pre, pre_b, cat_, 128, 0, cattf);
    launch_mma<64,64,1,2>(ftf + (size_t)BB*64*HWSZ, 64, 0, wp_pre, pre_b, cat_, 128, 64, cattf);

    // featcompressor layer1 + IN(+round) 
    launch_mma<128,128,1,0>(cattf, 128, 0, wp_fc1, nullptr, x128, 128, 0, nullptr);
    instnorm_lrelu_kernel<<<BB*128, 256>>>(x128, fc1_g, fc1_be, 128, 1);

    // featcompressor layer2 -> corr channels 0..63 (rounded)
    launch_mma<64,128,1,1>(x128, 128, 0, wp_fc2, fc2_b, corr_, 128, 0, nullptr);

    // gaussian blur of f1 (raw cat)
    {
        int n = BB*64*HWSZ;
        blur_h_kernel<<<(n+255)/256, 256>>>(cat_, 128, 0, tmp_, 64, n);
        blur_v_kernel<<<(n+255)/256, 256>>>(tmp_, f1s, n);
    }

    // local correlation -> corr channels 64..112, normalize (+round)
    zero_lcsum_kernel<<<1, 32>>>(lcsum);
    corr_kernel<<<dim3(WW/16, HH/16, BB), 256>>>(f1s, cat_, corr_, lcsum);
    {
        int n = BB*49*HWSZ;
        lcnorm_kernel<<<(n+255)/256, 256>>>(corr_, lcsum, n);
    }

    // estimator stack
    launch_mma<64,128,1,0>(corr_, 128, 0, wp_e1, nullptr, x64, 64, 0, nullptr);
    instnorm_lrelu_kernel<<<BB*64, 256>>>(x64, e1_g, e1_be, 64, 1);

    launch_mma<32,64,2,0>(x64, 64, 0, wp_e2, nullptr, x32, 32, 0, nullptr);
    instnorm_lrelu_kernel<<<BB*32, 256>>>(x32, e2_g, e2_be, 32, 1);

    launch_mma<16,32,4,0>(x32, 32, 0, wp_e3, nullptr, x16, 16, 0, nullptr);
    instnorm_lrelu_kernel<<<BB*16, 256>>>(x16, e3_g, e3_be, 16, 0);   // head needs raw

    // flow head (tiny, FFMA2 direct conv)
    {
        dim3 grid(1, (WW/C_TW)*(HH/C_TH), BB);
        conv3x3_kernel<1><<<grid, C_NT>>>(x16, 16, 16, 0, head_w, head_b, head_, 2, 2, 0);
    }

    // final blur -> output
    {
        int n = BB*2*HWSZ;
        blur_h_kernel<<<(n+255)/256, 256>>>(head_, 2, 0, tmp_, 2, n);
        blur_v_kernel<<<(n+255)/256, 256>>>(tmp_, out, n);
    }
}

// round 9
// speedup vs baseline: 1.6160x; 1.1079x over previous
#include <cuda_runtime.h>
#include <math.h>

// ---------------- problem constants ----------------
#define BB 4
#define HH 256
#define WW 256
#define HWSZ (HH*WW)

typedef unsigned long long ull;

// ---------------- scratch buffers ----------------
__device__ float g_cat   [(size_t)BB*128*HWSZ]; // raw f1|f2 (for blur/corr)
__device__ float g_cattf [(size_t)BB*128*HWSZ]; // tf32-rounded f1|f2 (for fc1)
__device__ float g_x128  [(size_t)BB*128*HWSZ];
__device__ float g_corr  [(size_t)BB*128*HWSZ]; // feat | lc | zero pad
__device__ float g_f1s   [(size_t)BB*64*HWSZ];
__device__ float g_tmp   [(size_t)BB*64*HWSZ];
__device__ float g_x64   [(size_t)BB*64*HWSZ];
__device__ float g_x32   [(size_t)BB*32*HWSZ];
__device__ float g_x16   [(size_t)BB*16*HWSZ];
__device__ float g_head  [(size_t)BB*2*HWSZ];
__device__ float g_lcsum[BB];
__device__ float g_wp[36864 + 147456 + 73728 + 73728 + 18432 + 4608];

__constant__ float GK[7] = {0.03663285f, 0.11128102f, 0.21674443f, 0.27068263f,
                            0.21674443f, 0.11128102f, 0.03663285f};

// ---------------- helpers ----------------
__device__ __forceinline__ unsigned f2tf(float f) {
    unsigned r; asm("cvt.rna.tf32.f32 %0, %1;" : "=r"(r) : "f"(f)); return r;
}
__device__ __forceinline__ float rndtf(float f) { return __uint_as_float(f2tf(f)); }
__device__ __forceinline__ void mma8(float* d, const unsigned* a, const unsigned* b) {
    asm volatile("mma.sync.aligned.m16n8k8.row.col.f32.tf32.tf32.f32 "
        "{%0,%1,%2,%3}, {%4,%5,%6,%7}, {%8,%9}, {%0,%1,%2,%3};\n"
        : "+f"(d[0]), "+f"(d[1]), "+f"(d[2]), "+f"(d[3])
        : "r"(a[0]), "r"(a[1]), "r"(a[2]), "r"(a[3]), "r"(b[0]), "r"(b[1]));
}
__device__ __forceinline__ ull pk2(float lo, float hi) {
    ull r; asm("mov.b64 %0, {%1, %2};" : "=l"(r) : "f"(lo), "f"(hi)); return r;
}
__device__ __forceinline__ void up2(float& lo, float& hi, ull v) {
    asm("mov.b64 {%0, %1}, %2;" : "=f"(lo), "=f"(hi) : "l"(v));
}
__device__ __forceinline__ void fma2(ull& d, ull a, ull b) {
    asm("fma.rn.f32x2 %0, %1, %2, %0;" : "+l"(d) : "l"(a), "l"(b));
}
__device__ __forceinline__ ull add2(ull a, ull b) {
    ull r; asm("add.rn.f32x2 %0, %1, %2;" : "=l"(r) : "l"(a), "l"(b)); return r;
}
__device__ __forceinline__ unsigned smem_u32(const void* p) {
    return (unsigned)__cvta_generic_to_shared(p);
}
__device__ __forceinline__ void cpasync16(unsigned dst, const void* src) {
    asm volatile("cp.async.cg.shared.global [%0], [%1], 16;" :: "r"(dst), "l"(src));
}
__device__ __forceinline__ void cpasync16_z(unsigned dst, const void* src) {
    asm volatile("cp.async.cg.shared.global [%0], [%1], 16, 0;" :: "r"(dst), "l"(src));
}

// ---------------- merged weight prep, fragment-swizzled layout -------------
// wp layout per layer: [chunk][k9][ks][coblk][lane][4]
//   j0:(ci+0,co+0) j1:(ci+0,co+8) j2:(ci+4,co+0) j3:(ci+4,co+8)
//   ci = chunk*16 + ks*8 + (lane&3) (+4 if j>=2), co = coblk*16 + (lane>>2) (+8 if j&1)
__device__ __forceinline__ void prep_one(const float* src, float* dst, int r,
                                         int COUT, int CIN)
{
    int j     = r & 3;
    int lane  = (r >> 2) & 31;
    int t     = r >> 7;
    int nblk  = COUT >> 4;
    int coblk = t % nblk;  t /= nblk;
    int ks    = t & 1;     t >>= 1;
    int k9    = t % 9;
    int chunk = t / 9;
    int ci = chunk*16 + ks*8 + (lane & 3) + ((j >> 1) ? 4 : 0);
    int co = coblk*16 + (lane >> 2) + ((j & 1) ? 8 : 0);
    float v = (ci < CIN) ? src[((size_t)(co*CIN + ci))*9 + k9] : 0.f;
    dst[r] = rndtf(v);
}

__global__ void prep_all_kernel(const float* __restrict__ w_pre,
                                const float* __restrict__ w_fc1,
                                const float* __restrict__ w_fc2,
                                const float* __restrict__ w_e1,
                                const float* __restrict__ w_e2,
                                const float* __restrict__ w_e3,
                                float* __restrict__ wp)
{
    int idx = blockIdx.x*256 + threadIdx.x;
    if      (idx < 36864)  prep_one(w_pre, wp,          idx,          64, 64);
    else if (idx < 184320) prep_one(w_fc1, wp + 36864,  idx - 36864, 128, 128);
    else if (idx < 258048) prep_one(w_fc2, wp + 184320, idx - 184320, 64, 128);
    else if (idx < 331776) prep_one(w_e1,  wp + 258048, idx - 258048, 64, 113);
    else if (idx < 350208) prep_one(w_e2,  wp + 331776, idx - 331776, 32, 64);
    else if (idx < 354816) prep_one(w_e3,  wp + 350208, idx - 350208, 16, 32);
}

// ---------------- tf32 tensor-core 3x3 conv --------------------------------
#define KC 16
#define PWD 136

// WMODE: 0 = raw out; 1 = rounded out; 2 = raw out + rounded out2
// FCVT:  1 = fill converts raw fp32 -> tf32; 0 = input already rounded (pure copy)
template<int COUT, int CIN, int DIL, int WMODE, int FCVT>
__global__ __launch_bounds__(256)
void conv_mma(const float* __restrict__ in, int CinS, int cinOff,
              const float* __restrict__ wp, const float* __restrict__ bias,
              float* __restrict__ out, int CoutS, int coutOff,
              float* __restrict__ out2)
{
    constexpr int WM = (COUT >= 32) ? 32 : COUT;
    constexpr int NMW = COUT / WM;
    constexpr int NNW = 8 / NMW;
    constexpr int WN  = 128 / NNW;
    constexpr int MTILES = WM / 16;
    constexpr int NTILES = WN / 8;
    constexpr int NBLK = COUT / 16;
    constexpr int WCHUNK4 = 9*2*NBLK*32;   // 16B units per ci-chunk of weights
    constexpr int HSH = (DIL==1) ? 1 : (DIL==2) ? 2 : 3;
    constexpr int NHALO = 3*KC*2*DIL;
    constexpr int MBASE = 4 - DIL;

    extern __shared__ __align__(16) unsigned smem_u[];
    unsigned* s_in = smem_u;                    // [3*KC][PWD], main px at +4
    unsigned* s_w  = smem_u + 3*KC*PWD;         // [9][2][NBLK][32][4]

    const int tid = threadIdx.x;
    const int x0  = blockIdx.x * 128;
    const int y   = blockIdx.y;
    const int bz  = blockIdx.z;
    const int wid = tid >> 5, lane = tid & 31;
    const int g = lane >> 2, c = lane & 3;
    const int wm = wid % NMW, wn = wid / NMW;

    float acc[MTILES][NTILES][4];
#pragma unroll
    for (int mt=0; mt<MTILES; mt++)
#pragma unroll
        for (int nt=0; nt<NTILES; nt++)
#pragma unroll
            for (int r=0; r<4; r++) acc[mt][nt][r] = 0.f;

#pragma unroll 1
    for (int ci0 = 0; ci0 < CIN; ci0 += KC) {
        __syncthreads();
        // weights: linear cp.async copy of one swizzled chunk
        {
            const float4* wsrc = (const float4*)wp + (size_t)(ci0 >> 4)*WCHUNK4;
            for (int idx = tid; idx < WCHUNK4; idx += 256)
                cpasync16(smem_u32((float*)s_w + idx*4), wsrc + idx);
        }
        const float* ibase = in + ((size_t)(bz*CinS + cinOff + ci0))*HWSZ;
        if (FCVT) {
            asm volatile("cp.async.commit_group;");
            const int pxm = tid & 127;
            const int r0  = tid >> 7;
#pragma unroll
            for (int it = 0; it < 24; it++) {
                const int rowIdx = it*2 + r0;
                const int row = rowIdx >> 4;
                const int ci  = rowIdx & 15;
                const int gy  = y + (row-1)*DIL;
                float v = 0.f;
                if ((unsigned)gy < HH)
                    v = ibase[(size_t)ci*HWSZ + (size_t)gy*WW + x0 + pxm];
                s_in[rowIdx*PWD + 4 + pxm] = f2tf(v);
            }
            for (int idx = tid; idx < NHALO; idx += 256) {
                const int off    = idx & (2*DIL - 1);
                const int rowIdx = idx >> HSH;
                const int row = rowIdx >> 4;
                const int ci  = rowIdx & 15;
                const int px  = (off < DIL) ? (4 - DIL + off) : (132 + off - DIL);
                const int gx  = x0 + ((off < DIL) ? (off - DIL) : (128 + off - DIL));
                const int gy  = y + (row-1)*DIL;
                float v = 0.f;
                if ((unsigned)gy < HH && (unsigned)gx < WW)
                    v = ibase[(size_t)ci*HWSZ + (size_t)gy*WW + gx];
                s_in[rowIdx*PWD + px] = f2tf(v);
            }
        } else {
#pragma unroll
            for (int it = 0; it < 6; it++) {
                const int idx    = tid + it*256;
                const int chunk  = idx & 31;
                const int rowIdx = idx >> 5;
                const int row = rowIdx >> 4;
                const int ci  = rowIdx & 15;
                const int gy  = y + (row-1)*DIL;
                unsigned dst = smem_u32((float*)s_in + rowIdx*PWD + 4 + chunk*4);
                const float* src = ibase + (size_t)ci*HWSZ
                                 + (size_t)min(max(gy,0),HH-1)*WW + x0 + chunk*4;
                if ((unsigned)gy < HH) cpasync16(dst, src);
                else                   cpasync16_z(dst, src);
            }
            asm volatile("cp.async.commit_group;");
            for (int idx = tid; idx < NHALO; idx += 256) {
                const int off    = idx & (2*DIL - 1);
                const int rowIdx = idx >> HSH;
                const int row = rowIdx >> 4;
                const int ci  = rowIdx & 15;
                const int px  = (off < DIL) ? (4 - DIL + off) : (132 + off - DIL);
                const int gx  = x0 + ((off < DIL) ? (off - DIL) : (128 + off - DIL));
                const int gy  = y + (row-1)*DIL;
                float v = 0.f;
                if ((unsigned)gy < HH && (unsigned)gx < WW)
                    v = ibase[(size_t)ci*HWSZ + (size_t)gy*WW + gx];
                ((float*)s_in)[rowIdx*PWD + px] = v;
            }
        }
        asm volatile("cp.async.wait_group 0;" ::: "memory");
        __syncthreads();

#pragma unroll
        for (int ky=0; ky<3; ky++) {
#pragma unroll
            for (int kx=0; kx<3; kx++) {
                const int xoff = MBASE + kx*DIL + wn*WN;
#pragma unroll
                for (int ks=0; ks<KC/8; ks++) {
                    unsigned a[MTILES][4];
#pragma unroll
                    for (int mt=0; mt<MTILES; mt++) {
                        const uint4 av = *(const uint4*)(s_w +
                            ((((ky*3+kx)*2 + ks)*NBLK + wm*MTILES + mt)*32 + lane)*4);
                        a[mt][0] = av.x; a[mt][1] = av.y; a[mt][2] = av.z; a[mt][3] = av.w;
                    }
#pragma unroll
                    for (int nt=0; nt<NTILES; nt++) {
                        const unsigned* bb = s_in + (ky*KC + ks*8 + c)*PWD + xoff + nt*8 + g;
                        unsigned bv[2];
                        bv[0] = bb[0];
                        bv[1] = bb[4*PWD];
#pragma unroll
                        for (int mt=0; mt<MTILES; mt++)
                            mma8(acc[mt][nt], a[mt], bv);
                    }
                }
            }
        }
    }

    // epilogue -> NCHW
#pragma unroll
    for (int mt=0; mt<MTILES; mt++) {
        const int co0 = wm*WM + mt*16 + g;
        const float b0v = bias ? bias[co0]     : 0.f;
        const float b1v = bias ? bias[co0 + 8] : 0.f;
        const size_t obase = ((size_t)(bz*CoutS + coutOff + co0))*HWSZ + (size_t)y*WW + x0 + wn*WN;
        float* o0 = out + obase;
        float* o1 = o0 + (size_t)8*HWSZ;
#pragma unroll
        for (int nt=0; nt<NTILES; nt++) {
            const int px = nt*8 + 2*c;
            float2 v0, v1;
            v0.x = acc[mt][nt][0] + b0v; v0.y = acc[mt][nt][1] + b0v;
            v1.x = acc[mt][nt][2] + b1v; v1.y = acc[mt][nt][3] + b1v;
            if (WMODE == 1) {
                v0.x = rndtf(v0.x); v0.y = rndtf(v0.y);
                v1.x = rndtf(v1.x); v1.y = rndtf(v1.y);
            }
            *(float2*)(o0 + px) = v0;
            *(float2*)(o1 + px) = v1;
            if (WMODE == 2) {
                float2 r0, r1;
                r0.x = rndtf(v0.x); r0.y = rndtf(v0.y);
                r1.x = rndtf(v1.x); r1.y = rndtf(v1.y);
                *(float2*)(out2 + obase + px) = r0;
                *(float2*)(out2 + obase + (size_t)8*HWSZ + px) = r1;
            }
        }
    }
}

// ---------------- tiny FFMA2 conv for the 16->2 head -----------------------
#define C_NT 128
#define C_TH 16
#define C_TW 64
#define C_CO 8

template<int DIL>
__global__ __launch_bounds__(C_NT, 3)
void conv3x3_kernel(const float* __restrict__ in, int Cin, int CinS, int cinOff,
                    const float* __restrict__ wgt, const float* __restrict__ bias,
                    float* __restrict__ out, int Cout, int CoutS, int coutOff)
{
    constexpr int TLW = C_TW + 2*DIL;
    constexpr int TLH = C_TH + 2*DIL;
    constexpr int NE  = (DIL==1) ? 5 : (DIL==2) ? 6 : 8;
    __shared__ __align__(16) float s_in[2][TLH*TLW];
    __shared__ __align__(16) ull   s_w2[2][C_CO*9];

    const int cb   = blockIdx.x * C_CO;
    const int tile = blockIdx.y;
    const int x0g  = (tile & 3) * C_TW;
    const int y0g  = (tile >> 2) * C_TH;
    const int b    = blockIdx.z;
    const int tid  = threadIdx.x;
    const int ty   = tid >> 3;
    const int xo   = (tid & 7) * 8;

    ull acc[C_CO][4];
#pragma unroll
    for (int co=0;co<C_CO;co++)
#pragma unroll
        for (int p=0;p<4;p++) acc[co][p] = 0ull;

    for (int ci0 = 0; ci0 < Cin; ci0 += 2) {
#pragma unroll
        for (int cc = 0; cc < 2; cc++) {
            const int ci = ci0 + cc;
            const float* ip = in + ((size_t)(b*CinS + cinOff + ci))*HWSZ;
            const bool cv = (ci < Cin);
            for (int idx = tid; idx < TLH*TLW; idx += C_NT) {
                int r = idx / TLW, cx = idx - r*TLW;
                int gy = y0g + r - DIL, gx = x0g + cx - DIL;
                float v = 0.f;
                if (cv && gy >= 0 && gy < HH && gx >= 0 && gx < WW) v = ip[gy*WW + gx];
                s_in[cc][idx] = v;
            }
        }
        for (int idx = tid; idx < 2*C_CO*9; idx += C_NT) {
            int cc = idx / (C_CO*9);
            int t  = idx - cc*(C_CO*9);
            int co = t / 9, k = t - co*9;
            int gci = ci0 + cc, gco = cb + co;
            float w = (gci < Cin && gco < Cout) ? wgt[((size_t)gco*Cin + gci)*9 + k] : 0.f;
            s_w2[cc][t] = pk2(w, w);
        }
        __syncthreads();
#pragma unroll
        for (int cc = 0; cc < 2; cc++) {
#pragma unroll
            for (int ky = 0; ky < 3; ky++) {
                const float* rowp = &s_in[cc][(ty + ky*DIL)*TLW + xo];
                ull E[NE];
#pragma unroll
                for (int i = 0; i < NE; i++) E[i] = *(const ull*)(rowp + 2*i);
                ull O[4];
                if (DIL == 1) {
#pragma unroll
                    for (int i = 0; i < 4; i++) O[i] = pk2(rowp[2*i+1], rowp[2*i+2]);
                }
#pragma unroll
                for (int kx = 0; kx < 3; kx++) {
                    ull vv[4];
                    if (DIL == 1) {
                        if (kx == 0)      { vv[0]=E[0]; vv[1]=E[1]; vv[2]=E[2]; vv[3]=E[3]; }
                        else if (kx == 1) { vv[0]=O[0]; vv[1]=O[1]; vv[2]=O[2]; vv[3]=O[3]; }
                        else              { vv[0]=E[1]; vv[1]=E[2]; vv[2]=E[3]; vv[3]=E[4]; }
                    } else {
                        const int base = kx*(DIL/2);
#pragma unroll
                        for (int p = 0; p < 4; p++) vv[p] = E[base + p];
                    }
#pragma unroll
                    for (int co = 0; co < C_CO; co++) {
                        ull w = s_w2[cc][co*9 + ky*3 + kx];
#pragma unroll
                        for (int p = 0; p < 4; p++) fma2(acc[co][p], w, vv[p]);
                    }
                }
            }
        }
        __syncthreads();
    }
#pragma unroll
    for (int co = 0; co < C_CO; co++) {
        int gco = cb + co;
        if (gco >= Cout) break;
        float bv = bias ? bias[gco] : 0.f;
        ull bv2 = pk2(bv, bv);
        float* op = out + ((size_t)(b*CoutS + coutOff + gco))*HWSZ + (y0g + ty)*WW + x0g + xo;
#pragma unroll
        for (int p = 0; p < 4; p++) {
            ull r = add2(acc[co][p], bv2);
            *(ull*)(op + 2*p) = r;
        }
    }
}

// ---------------- instance norm + leaky relu (in place, float4) ----------
__global__ void instnorm_lrelu_kernel(float* __restrict__ x, const float* __restrict__ gamma,
                                      const float* __restrict__ beta, int C, int rnd)
{
    const int bc = blockIdx.x;
    float4* p = (float4*)(x + (size_t)bc*HWSZ);
    const int N4 = HWSZ/4;
    const int tid = threadIdx.x;
    float s = 0.f, s2 = 0.f;
    for (int i = tid; i < N4; i += 256) {
        float4 v = p[i];
        s  += v.x + v.y + v.z + v.w;
        s2 += v.x*v.x + v.y*v.y + v.z*v.z + v.w*v.w;
    }
    __shared__ float rs[256], rq[256];
    rs[tid] = s; rq[tid] = s2; __syncthreads();
    for (int off = 128; off > 0; off >>= 1) {
        if (tid < off) { rs[tid] += rs[tid+off]; rq[tid] += rq[tid+off]; }
        __syncthreads();
    }
    const float mu  = rs[0]*(1.f/HWSZ);
    const float var = rq[0]*(1.f/HWSZ) - mu*mu;
    const float inv = rsqrtf(var + 1e-5f);
    const int c = bc % C;
    const float ga = gamma[c]*inv, be = beta[c];
    for (int i = tid; i < N4; i += 256) {
        float4 v = p[i];
        v.x = (v.x-mu)*ga + be; v.x = (v.x >= 0.f) ? v.x : 0.2f*v.x;
        v.y = (v.y-mu)*ga + be; v.y = (v.y >= 0.f) ? v.y : 0.2f*v.y;
        v.z = (v.z-mu)*ga + be; v.z = (v.z >= 0.f) ? v.z : 0.2f*v.z;
        v.w = (v.w-mu)*ga + be; v.w = (v.w >= 0.f) ? v.w : 0.2f*v.w;
        if (rnd) {
            v.x = rndtf(v.x); v.y = rndtf(v.y); v.z = rndtf(v.z); v.w = rndtf(v.w);
        }
        p[i] = v;
    }
}

// ---------------- separable gaussian blur, replicate padding ------------
__global__ void blur_h_kernel(const float* __restrict__ in, int CinS, int cinOff,
                              float* __restrict__ out, int C, int n)
{
    int idx = blockIdx.x*blockDim.x + threadIdx.x;
    if (idx >= n) return;
    int x = idx % WW;
    int y = (idx / WW) % HH;
    int bc = idx / HWSZ;
    int b = bc / C, c = bc % C;
    const float* ip = in + ((size_t)(b*CinS + cinOff + c))*HWSZ + y*WW;
    float s = 0.f;
#pragma unroll
    for (int t = 0; t < 7; t++) {
        int xx = x + t - 3;
        xx = min(max(xx, 0), WW-1);
        s += GK[t]*ip[xx];
    }
    out[(size_t)bc*HWSZ + y*WW + x] = s;
}

__global__ void blur_v_kernel(const float* __restrict__ in, float* __restrict__ out, int n)
{
    int idx = blockIdx.x*blockDim.x + threadIdx.x;
    if (idx >= n) return;
    int x = idx % WW;
    int y = (idx / WW) % HH;
    int bc = idx / HWSZ;
    const float* ip = in + (size_t)bc*HWSZ;
    float s = 0.f;
#pragma unroll
    for (int t = 0; t < 7; t++) {
        int yy = y + t - 3;
        yy = min(max(yy, 0), HH-1);
        s += GK[t]*ip[yy*WW + x];
    }
    out[(size_t)bc*HWSZ + y*WW + x] = s;
}

// ---------------- local correlation: 2 px/thread, window reuse, FFMA2 ------
#define CW 40
__global__ void corr_kernel(const float* __restrict__ f1s, const float* __restrict__ f2base,
                            float* __restrict__ out, float* __restrict__ lcsum)
{
    __shared__ float s1[22*CW];
    __shared__ float red[256];
    const int bx = blockIdx.x, by = blockIdx.y, b = blockIdx.z;
    const int tid = threadIdx.x;
    const int ty = tid >> 4, tx = tid & 15;
    const int gy = by*16 + ty, gx = bx*32 + tx*2;

    ull acc2[49];
#pragma unroll
    for (int k = 0; k < 49; k++) acc2[k] = 0ull;

    for (int c = 0; c < 64; c++) {
        const float* p1 = f1s    + ((size_t)(b*64  + c))*HWSZ;
        const float* p2 = f2base + ((size_t)(b*128 + 64 + c))*HWSZ;
        for (int idx = tid; idx < 22*CW; idx += 256) {
            int r = idx / CW, cc = idx - r*CW;
            int yy = by*16 + r - 3, xx = bx*32 + cc - 3;
            s1[idx] = (yy >= 0 && yy < HH && xx >= 0 && xx < WW) ? p1[yy*WW+xx] : 0.f;
        }
        __syncthreads();
        const float v2a = p2[gy*WW + gx];
        const float v2b = p2[gy*WW + gx + 1];
#pragma unroll
        for (int i = 0; i < 7; i++) {
            const float* row = &s1[(ty+i)*CW + tx*2];
            float r[8];
#pragma unroll
            for (int q = 0; q < 8; q++) r[q] = row[q];
#pragma unroll
            for (int j = 0; j < 7; j++) {
                float d0 = v2a - r[j];
                float d1 = v2b - r[j+1];
                ull d = pk2(d0, d1);
                fma2(acc2[i*7+j], d, d);
            }
        }
        __syncthreads();
    }
    float tsum = 0.f;
#pragma unroll
    for (int k = 0; k < 49; k++) {
        float lo, hi; up2(lo, hi, acc2[k]);
        float2 lc; lc.x = lo*(1.f/64.f); lc.y = hi*(1.f/64.f);
        *(float2*)&out[((size_t)(b*128 + 64 + k))*HWSZ + gy*WW + gx] = lc;
        tsum += lc.x + lc.y;
    }
    red[tid] = tsum; __syncthreads();
    for (int off = 128; off > 0; off >>= 1) {
        if (tid < off) red[tid] += red[tid+off];
        __syncthreads();
    }
    if (tid == 0) atomicAdd(&lcsum[b], red[0]);
}

__global__ void zero_lcsum_kernel(float* lcsum)
{
    if (threadIdx.x < BB) lcsum[threadIdx.x] = 0.f;
}

__global__ void lcnorm_kernel(float* __restrict__ corr, const float* __restrict__ lcsum, int n)
{
    int idx = blockIdx.x*blockDim.x + threadIdx.x;
    if (idx >= n) return;
    int b = idx / (49*HWSZ);
    int r = idx - b*(49*HWSZ);
    float mean = lcsum[b]*(1.f/(49.f*HWSZ));
    float s = 1.f/(mean + 1e-6f);
    float* p = &corr[((size_t)b*128 + 64)*HWSZ + r];
    *p = rndtf(*p * s);
}

// ---------------- host side ----------------
template<int COUT, int CIN, int DIL, int WMODE, int FCVT>
static void launch_mma(const float* in, int CinS, int cinOff,
                       const float* wp, const float* bias,
                       float* out, int CoutS, int coutOff, float* out2)
{
    const int smem = (3*KC*PWD + 9*2*(COUT/16)*128)*4;
    cudaFuncSetAttribute(conv_mma<COUT,CIN,DIL,WMODE,FCVT>,
                         cudaFuncAttributeMaxDynamicSharedMemorySize, smem);
    conv_mma<COUT,CIN,DIL,WMODE,FCVT><<<dim3(2, HH, BB), 256, smem>>>(
        in, CinS, cinOff, wp, bias, out, CoutS, coutOff, out2);
}

extern "C" void kernel_launch(void* const* d_in, const int* in_sizes, int n_in,
                              void* d_out, int out_size)
{
    const float* feat1  = (const float*)d_in[0];
    const float* feat2  = (const float*)d_in[1];
    const float* pre_w  = (const float*)d_in[2];
    const float* pre_b  = (const float*)d_in[3];
    const float* fc1_w  = (const float*)d_in[4];
    const float* fc1_g  = (const float*)d_in[5];
    const float* fc1_be = (const float*)d_in[6];
    const float* fc2_w  = (const float*)d_in[7];
    const float* fc2_b  = (const float*)d_in[8];
    const float* e1_w   = (const float*)d_in[9];
    const float* e1_g   = (const float*)d_in[10];
    const float* e1_be  = (const float*)d_in[11];
    const float* e2_w   = (const float*)d_in[12];
    const float* e2_g   = (const float*)d_in[13];
    const float* e2_be  = (const float*)d_in[14];
    const float* e3_w   = (const float*)d_in[15];
    const float* e3_g   = (const float*)d_in[16];
    const float* e3_be  = (const float*)d_in[17];
    const float* head_w = (const float*)d_in[18];
    const float* head_b = (const float*)d_in[19];
    float* out = (float*)d_out;

    float *cat_, *cattf, *x128, *corr_, *f1s, *tmp_, *x64, *x32, *x16, *head_, *lcsum, *wpb;
    cudaGetSymbolAddress((void**)&cat_,  g_cat);
    cudaGetSymbolAddress((void**)&cattf, g_cattf);
    cudaGetSymbolAddress((void**)&x128,  g_x128);
    cudaGetSymbolAddress((void**)&corr_, g_corr);
    cudaGetSymbolAddress((void**)&f1s,   g_f1s);
    cudaGetSymbolAddress((void**)&tmp_,  g_tmp);
    cudaGetSymbolAddress((void**)&x64,   g_x64);
    cudaGetSymbolAddress((void**)&x32,   g_x32);
    cudaGetSymbolAddress((void**)&x16,   g_x16);
    cudaGetSymbolAddress((void**)&head_, g_head);
    cudaGetSymbolAddress((void**)&lcsum, g_lcsum);
    cudaGetSymbolAddress((void**)&wpb,   g_wp);

    float* wp_pre = wpb;
    float* wp_fc1 = wpb + 36864;
    float* wp_fc2 = wpb + 184320;
    float* wp_e1  = wpb + 258048;
    float* wp_e2  = wpb + 331776;
    float* wp_e3  = wpb + 350208;

    // weight prep (fragment-swizzled, tf32, ci-padded)
    prep_all_kernel<<<(354816 + 255)/256, 256>>>(pre_w, fc1_w, fc2_w, e1_w, e2_w, e3_w, wpb);

    // preprocessor (cvt fill from raw feats) -> cat (raw) + cattf (rounded)
    launch_mma<64,64,1,2,1>(feat1, 64, 0, wp_pre, pre_b, cat_, 128, 0, cattf);
    launch_mma<64,64,1,2,1>(feat2, 64, 0, wp_pre, pre_b, cat_, 128, 64, cattf);

    // featcompressor layer1 + IN(+round)
    launch_mma<128,128,1,0,0>(cattf, 128, 0, wp_fc1, nullptr, x128, 128, 0, nullptr);
    instnorm_lrelu_kernel<<<BB*128, 256>>>(x128, fc1_g, fc1_be, 128, 1);

    // featcompressor layer2 -> corr channels 0..63 (rounded)
    launch_mma<64,128,1,1,0>(x128, 128, 0, wp_fc2, fc2_b, corr_, 128, 0, nullptr);

    // gaussian blur of f1 (raw cat)
    {
        int n = BB*64*HWSZ;
        blur_h_kernel<<<(n+255)/256, 256>>>(cat_, 128, 0, tmp_, 64, n);
        blur_v_kernel<<<(n+255)/256, 256>>>(tmp_, f1s, n);
    }

    // local correlation -> corr channels 64..112, normalize (+round)
    zero_lcsum_kernel<<<1, 32>>>(lcsum);
    corr_kernel<<<dim3(WW/32, HH/16, BB), 256>>>(f1s, cat_, corr_, lcsum);
    {
        int n = BB*49*HWSZ;
        lcnorm_kernel<<<(n+255)/256, 256>>>(corr_, lcsum, n);
    }

    // estimator stack
    launch_mma<64,128,1,0,0>(corr_, 128, 0, wp_e1, nullptr, x64, 64, 0, nullptr);
    instnorm_lrelu_kernel<<<BB*64, 256>>>(x64, e1_g, e1_be, 64, 1);

    launch_mma<32,64,2,0,0>(x64, 64, 0, wp_e2, nullptr, x32, 32, 0, nullptr);
    instnorm_lrelu_kernel<<<BB*32, 256>>>(x32, e2_g, e2_be, 32, 1);

    launch_mma<16,32,4,0,0>(x32, 32, 0, wp_e3, nullptr, x16, 16, 0, nullptr);
    instnorm_lrelu_kernel<<<BB*16, 256>>>(x16, e3_g, e3_be, 16, 0);   // head needs raw

    // flow head (tiny, FFMA2 direct conv)
    {
        dim3 grid(1, (WW/C_TW)*(HH/C_TH), BB);
        conv3x3_kernel<1><<<grid, C_NT>>>(x16, 16, 16, 0, head_w, head_b, head_, 2, 2, 0);
    }

    // final blur -> output
    {
        int n = BB*2*HWSZ;
        blur_h_kernel<<<(n+255)/256, 256>>>(head_, 2, 0, tmp_, 2, n);
        blur_v_kernel<<<(n+255)/256, 256>>>(tmp_, out, n);
    }
}

// round 12
// speedup vs baseline: 1.6547x; 1.0240x over previous
#include <cuda_runtime.h>
#include <math.h>

// ---------------- problem constants ----------------
#define BB 4
#define HH 256
#define WW 256
#define HWSZ (HH*WW)

typedef unsigned long long ull;

// ---------------- scratch buffers ----------------
__device__ float g_cat   [(size_t)BB*128*HWSZ]; // raw f1|f2 (for blur/corr)
__device__ float g_cattf [(size_t)BB*128*HWSZ]; // tf32-rounded f1|f2 (for fc1)
__device__ float g_x128  [(size_t)BB*128*HWSZ];
__device__ float g_corr  [(size_t)BB*128*HWSZ]; // feat(rounded) | lc(raw) | zero
__device__ float g_f1s   [(size_t)BB*64*HWSZ];
__device__ float g_x64   [(size_t)BB*64*HWSZ];
__device__ float g_x32   [(size_t)BB*32*HWSZ];
__device__ float g_x16   [(size_t)BB*16*HWSZ];
__device__ float g_head  [(size_t)BB*2*HWSZ];
__device__ float g_lcsum[BB];
__device__ float g_wp[36864 + 147456 + 73728 + 73728 + 18432 + 4608];

__constant__ float GK[7] = {0.03663285f, 0.11128102f, 0.21674443f, 0.27068263f,
                            0.21674443f, 0.11128102f, 0.03663285f};

// ---------------- helpers ----------------
__device__ __forceinline__ unsigned f2tf(float f) {
    unsigned r; asm("cvt.rna.tf32.f32 %0, %1;" : "=r"(r) : "f"(f)); return r;
}
__device__ __forceinline__ float rndtf(float f) { return __uint_as_float(f2tf(f)); }
__device__ __forceinline__ void mma8(float* d, const unsigned* a, const unsigned* b) {
    asm volatile("mma.sync.aligned.m16n8k8.row.col.f32.tf32.tf32.f32 "
        "{%0,%1,%2,%3}, {%4,%5,%6,%7}, {%8,%9}, {%0,%1,%2,%3};\n"
        : "+f"(d[0]), "+f"(d[1]), "+f"(d[2]), "+f"(d[3])
        : "r"(a[0]), "r"(a[1]), "r"(a[2]), "r"(a[3]), "r"(b[0]), "r"(b[1]));
}
__device__ __forceinline__ ull pk2(float lo, float hi) {
    ull r; asm("mov.b64 %0, {%1, %2};" : "=l"(r) : "f"(lo), "f"(hi)); return r;
}
__device__ __forceinline__ void up2(float& lo, float& hi, ull v) {
    asm("mov.b64 {%0, %1}, %2;" : "=f"(lo), "=f"(hi) : "l"(v));
}
__device__ __forceinline__ void fma2(ull& d, ull a, ull b) {
    asm("fma.rn.f32x2 %0, %1, %2, %0;" : "+l"(d) : "l"(a), "l"(b));
}
__device__ __forceinline__ ull add2(ull a, ull b) {
    ull r; asm("add.rn.f32x2 %0, %1, %2;" : "=l"(r) : "l"(a), "l"(b)); return r;
}
__device__ __forceinline__ unsigned smem_u32(const void* p) {
    return (unsigned)__cvta_generic_to_shared(p);
}
__device__ __forceinline__ void cpasync16(unsigned dst, const void* src) {
    asm volatile("cp.async.cg.shared.global [%0], [%1], 16;" :: "r"(dst), "l"(src));
}
__device__ __forceinline__ void cpasync16_z(unsigned dst, const void* src) {
    asm volatile("cp.async.cg.shared.global [%0], [%1], 16, 0;" :: "r"(dst), "l"(src));
}

// ---------------- merged weight prep, fragment-swizzled layout -------------
__device__ __forceinline__ void prep_one(const float* src, float* dst, int r,
                                         int COUT, int CIN)
{
    int j     = r & 3;
    int lane  = (r >> 2) & 31;
    int t     = r >> 7;
    int nblk  = COUT >> 4;
    int coblk = t % nblk;  t /= nblk;
    int ks    = t & 1;     t >>= 1;
    int k9    = t % 9;
    int chunk = t / 9;
    int ci = chunk*16 + ks*8 + (lane & 3) + ((j >> 1) ? 4 : 0);
    int co = coblk*16 + (lane >> 2) + ((j & 1) ? 8 : 0);
    float v = (ci < CIN) ? src[((size_t)(co*CIN + ci))*9 + k9] : 0.f;
    dst[r] = rndtf(v);
}

__global__ void prep_all_kernel(const float* __restrict__ w_pre,
                                const float* __restrict__ w_fc1,
                                const float* __restrict__ w_fc2,
                                const float* __restrict__ w_e1,
                                const float* __restrict__ w_e2,
                                const float* __restrict__ w_e3,
                                float* __restrict__ wp)
{
    int idx = blockIdx.x*256 + threadIdx.x;
    if      (idx < 36864)  prep_one(w_pre, wp,          idx,          64, 64);
    else if (idx < 184320) prep_one(w_fc1, wp + 36864,  idx - 36864, 128, 128);
    else if (idx < 258048) prep_one(w_fc2, wp + 184320, idx - 184320, 64, 128);
    else if (idx < 331776) prep_one(w_e1,  wp + 258048, idx - 258048, 64, 113);
    else if (idx < 350208) prep_one(w_e2,  wp + 331776, idx - 331776, 32, 64);
    else if (idx < 354816) prep_one(w_e3,  wp + 350208, idx - 350208, 16, 32);
}

// ---------------- tf32 tensor-core 3x3 conv, 2 rows per CTA ----------------
#define KC 16
#define PWD 136

// WMODE: 0 raw out; 1 rounded out; 2 raw out + rounded out2
// FCVT:  0 pure copy; 1 cvt fill from raw; 2 copy ch<64, cvt*scale ch>=64 (<113), zero >=113
template<int COUT, int CIN, int DIL, int WMODE, int FCVT>
__global__ __launch_bounds__(512)
void conv_mma(const float* __restrict__ in, int CinS, int cinOff,
              const float* __restrict__ wp, const float* __restrict__ bias,
              float* __restrict__ out, int CoutS, int coutOff,
              float* __restrict__ out2, const float* __restrict__ lcs)
{
    constexpr int WM = (COUT >= 32) ? 32 : COUT;
    constexpr int NMW = COUT / WM;
    constexpr int NNW = 8 / NMW;
    constexpr int WN  = 128 / NNW;
    constexpr int MTILES = WM / 16;
    constexpr int NTILES = WN / 8;
    constexpr int NBLK = COUT / 16;
    constexpr int WCHUNK4 = 9*2*NBLK*32;        // 16B units of weights per chunk
    constexpr int NR = 2 + 2*DIL;               // input rows held
    constexpr int HSH = (DIL==1) ? 1 : (DIL==2) ? 2 : 3;
    constexpr int NHALO = NR*KC*2*DIL;
    constexpr int MBASE = 4 - DIL;

    extern __shared__ __align__(16) unsigned smem_u[];
    unsigned* s_in = smem_u;                    // [NR*KC][PWD], main px at +4
    unsigned* s_w  = smem_u + NR*KC*PWD;        // [9][2][NBLK][32][4]

    const int tid = threadIdx.x;
    const int x0  = blockIdx.x * 128;
    const int y0  = blockIdx.y * 2;
    const int bz  = blockIdx.z;
    const int wid = tid >> 5, lane = tid & 31;
    const int g = lane >> 2, c = lane & 3;
    const int wy = wid >> 3;
    const int w8 = wid & 7;
    const int wm = w8 % NMW, wn = w8 / NMW;

    float s_scale = 1.f;
    if (FCVT == 2) {
        float mean = lcs[bz]*(1.f/(49.f*HWSZ));
        s_scale = 1.f/(mean + 1e-6f);
    }

    float acc[MTILES][NTILES][4];
#pragma unroll
    for (int mt=0; mt<MTILES; mt++)
#pragma unroll
        for (int nt=0; nt<NTILES; nt++)
#pragma unroll
            for (int r=0; r<4; r++) acc[mt][nt][r] = 0.f;

#pragma unroll 1
    for (int ci0 = 0; ci0 < CIN; ci0 += KC) {
        __syncthreads();
        // weights: linear cp.async copy of one swizzled chunk
        {
            const float4* wsrc = (const float4*)wp + (size_t)(ci0 >> 4)*WCHUNK4;
            for (int idx = tid; idx < WCHUNK4; idx += 512)
                cpasync16(smem_u32((float*)s_w + idx*4), wsrc + idx);
        }
        const float* ibase = in + ((size_t)(bz*CinS + cinOff + ci0))*HWSZ;
        const bool async_chunk = (FCVT == 0) || (FCVT == 2 && ci0 < 64);
        if (async_chunk) {
#pragma unroll
            for (int it = 0; it < NR; it++) {
                const int idx    = tid + it*512;
                const int chunk  = idx & 31;
                const int rowIdx = idx >> 5;          // 0..NR*16-1
                const int row = rowIdx >> 4;
                const int ci  = rowIdx & 15;
                const int gy  = y0 - DIL + row;
                unsigned dst = smem_u32((float*)s_in + rowIdx*PWD + 4 + chunk*4);
                const float* src = ibase + (size_t)ci*HWSZ
                                 + (size_t)min(max(gy,0),HH-1)*WW + x0 + chunk*4;
                if ((unsigned)gy < HH) cpasync16(dst, src);
                else                   cpasync16_z(dst, src);
            }
            asm volatile("cp.async.commit_group;");
            for (int idx = tid; idx < NHALO; idx += 512) {
                const int off    = idx & (2*DIL - 1);
                const int rowIdx = idx >> HSH;
                const int row = rowIdx >> 4;
                const int ci  = rowIdx & 15;
                const int px  = (off < DIL) ? (4 - DIL + off) : (132 + off - DIL);
                const int gx  = x0 + ((off < DIL) ? (off - DIL) : (128 + off - DIL));
                const int gy  = y0 - DIL + row;
                float v = 0.f;
                if ((unsigned)gy < HH && (unsigned)gx < WW)
                    v = ibase[(size_t)ci*HWSZ + (size_t)gy*WW + gx];
                ((float*)s_in)[rowIdx*PWD + px] = v;
            }
        } else {
            asm volatile("cp.async.commit_group;");
            const int pxm = tid & 127;
            const int r0  = tid >> 7;                 // 0..3
#pragma unroll
            for (int it = 0; it < NR*4; it++) {
                const int rowIdx = it*4 + r0;
                const int row = rowIdx >> 4;
                const int ci  = rowIdx & 15;
                const int gy  = y0 - DIL + row;
                const int gci = ci0 + ci;
                float v = 0.f;
                bool ok = ((unsigned)gy < HH);
                if (FCVT == 2) ok = ok && (gci < 113);
                if (ok) {
                    float raw = ibase[(size_t)ci*HWSZ + (size_t)gy*WW + x0 + pxm];
                    v = rndtf((FCVT == 2) ? raw*s_scale : raw);
                }
                s_in[rowIdx*PWD + 4 + pxm] = __float_as_uint(v);
            }
            for (int idx = tid; idx < NHALO; idx += 512) {
                const int off    = idx & (2*DIL - 1);
                const int rowIdx = idx >> HSH;
                const int row = rowIdx >> 4;
                const int ci  = rowIdx & 15;
                const int px  = (off < DIL) ? (4 - DIL + off) : (132 + off - DIL);
                const int gx  = x0 + ((off < DIL) ? (off - DIL) : (128 + off - DIL));
                const int gy  = y0 - DIL + row;
                const int gci = ci0 + ci;
                float v = 0.f;
                bool ok = ((unsigned)gy < HH && (unsigned)gx < WW);
                if (FCVT == 2) ok = ok && (gci < 113);
                if (ok) {
                    float raw = ibase[(size_t)ci*HWSZ + (size_t)gy*WW + gx];
                    v = rndtf((FCVT == 2) ? raw*s_scale : raw);
                }
                s_in[rowIdx*PWD + px] = __float_as_uint(v);
            }
        }
        asm volatile("cp.async.wait_group 0;" ::: "memory");
        __syncthreads();

#pragma unroll
        for (int ky=0; ky<3; ky++) {
#pragma unroll
            for (int kx=0; kx<3; kx++) {
                const int xoff = MBASE + kx*DIL + wn*WN;
                const int srow = wy + ky*DIL;
#pragma unroll
                for (int ks=0; ks<KC/8; ks++) {
                    unsigned a[MTILES][4];
#pragma unroll
                    for (int mt=0; mt<MTILES; mt++) {
                        const uint4 av = *(const uint4*)(s_w +
                            ((((ky*3+kx)*2 + ks)*NBLK + wm*MTILES + mt)*32 + lane)*4);
                        a[mt][0] = av.x; a[mt][1] = av.y; a[mt][2] = av.z; a[mt][3] = av.w;
                    }
#pragma unroll
                    for (int nt=0; nt<NTILES; nt++) {
                        const unsigned* bb = s_in + (srow*KC + ks*8 + c)*PWD + xoff + nt*8 + g;
                        unsigned bv[2];
                        bv[0] = bb[0];
                        bv[1] = bb[4*PWD];
#pragma unroll
                        for (int mt=0; mt<MTILES; mt++)
                            mma8(acc[mt][nt], a[mt], bv);
                    }
                }
            }
        }
    }

    // epilogue -> NCHW
    const int y = y0 + wy;
#pragma unroll
    for (int mt=0; mt<MTILES; mt++) {
        const int co0 = wm*WM + mt*16 + g;
        const float b0v = bias ? bias[co0]     : 0.f;
        const float b1v = bias ? bias[co0 + 8] : 0.f;
        const size_t obase = ((size_t)(bz*CoutS + coutOff + co0))*HWSZ + (size_t)y*WW + x0 + wn*WN;
        float* o0 = out + obase;
        float* o1 = o0 + (size_t)8*HWSZ;
#pragma unroll
        for (int nt=0; nt<NTILES; nt++) {
            const int px = nt*8 + 2*c;
            float2 v0, v1;
            v0.x = acc[mt][nt][0] + b0v; v0.y = acc[mt][nt][1] + b0v;
            v1.x = acc[mt][nt][2] + b1v; v1.y = acc[mt][nt][3] + b1v;
            if (WMODE == 1) {
                v0.x = rndtf(v0.x); v0.y = rndtf(v0.y);
                v1.x = rndtf(v1.x); v1.y = rndtf(v1.y);
            }
            *(float2*)(o0 + px) = v0;
            *(float2*)(o1 + px) = v1;
            if (WMODE == 2) {
                float2 r0, r1;
                r0.x = rndtf(v0.x); r0.y = rndtf(v0.y);
                r1.x = rndtf(v1.x); r1.y = rndtf(v1.y);
                *(float2*)(out2 + obase + px) = r0;
                *(float2*)(out2 + obase + (size_t)8*HWSZ + px) = r1;
            }
        }
    }
}

// ---------------- tiny FFMA2 conv for the 16->2 head -----------------------
#define C_NT 128
#define C_TH 16
#define C_TW 64
#define C_CO 8

template<int DIL>
__global__ __launch_bounds__(C_NT, 3)
void conv3x3_kernel(const float* __restrict__ in, int Cin, int CinS, int cinOff,
                    const float* __restrict__ wgt, const float* __restrict__ bias,
                    float* __restrict__ out, int Cout, int CoutS, int coutOff)
{
    constexpr int TLW = C_TW + 2*DIL;
    constexpr int TLH = C_TH + 2*DIL;
    constexpr int NE  = (DIL==1) ? 5 : (DIL==2) ? 6 : 8;
    __shared__ __align__(16) float s_in[2][TLH*TLW];
    __shared__ __align__(16) ull   s_w2[2][C_CO*9];

    const int cb   = blockIdx.x * C_CO;
    const int tile = blockIdx.y;
    const int x0g  = (tile & 3) * C_TW;
    const int y0g  = (tile >> 2) * C_TH;
    const int b    = blockIdx.z;
    const int tid  = threadIdx.x;
    const int ty   = tid >> 3;
    const int xo   = (tid & 7) * 8;

    ull acc[C_CO][4];
#pragma unroll
    for (int co=0;co<C_CO;co++)
#pragma unroll
        for (int p=0;p<4;p++) acc[co][p] = 0ull;

    for (int ci0 = 0; ci0 < Cin; ci0 += 2) {
#pragma unroll
        for (int cc = 0; cc < 2; cc++) {
            const int ci = ci0 + cc;
            const float* ip = in + ((size_t)(b*CinS + cinOff + ci))*HWSZ;
            const bool cv = (ci < Cin);
            for (int idx = tid; idx < TLH*TLW; idx += C_NT) {
                int r = idx / TLW, cx = idx - r*TLW;
                int gy = y0g + r - DIL, gx = x0g + cx - DIL;
                float v = 0.f;
                if (cv && gy >= 0 && gy < HH && gx >= 0 && gx < WW) v = ip[gy*WW + gx];
                s_in[cc][idx] = v;
            }
        }
        for (int idx = tid; idx < 2*C_CO*9; idx += C_NT) {
            int cc = idx / (C_CO*9);
            int t  = idx - cc*(C_CO*9);
            int co = t / 9, k = t - co*9;
            int gci = ci0 + cc, gco = cb + co;
            float w = (gci < Cin && gco < Cout) ? wgt[((size_t)gco*Cin + gci)*9 + k] : 0.f;
            s_w2[cc][t] = pk2(w, w);
        }
        __syncthreads();
#pragma unroll
        for (int cc = 0; cc < 2; cc++) {
#pragma unroll
            for (int ky = 0; ky < 3; ky++) {
                const float* rowp = &s_in[cc][(ty + ky*DIL)*TLW + xo];
                ull E[NE];
#pragma unroll
                for (int i = 0; i < NE; i++) E[i] = *(const ull*)(rowp + 2*i);
                ull O[4];
                if (DIL == 1) {
#pragma unroll
                    for (int i = 0; i < 4; i++) O[i] = pk2(rowp[2*i+1], rowp[2*i+2]);
                }
#pragma unroll
                for (int kx = 0; kx < 3; kx++) {
                    ull vv[4];
                    if (DIL == 1) {
                        if (kx == 0)      { vv[0]=E[0]; vv[1]=E[1]; vv[2]=E[2]; vv[3]=E[3]; }
                        else if (kx == 1) { vv[0]=O[0]; vv[1]=O[1]; vv[2]=O[2]; vv[3]=O[3]; }
                        else              { vv[0]=E[1]; vv[1]=E[2]; vv[2]=E[3]; vv[3]=E[4]; }
                    } else {
                        const int base = kx*(DIL/2);
#pragma unroll
                        for (int p = 0; p < 4; p++) vv[p] = E[base + p];
                    }
#pragma unroll
                    for (int co = 0; co < C_CO; co++) {
                        ull w = s_w2[cc][co*9 + ky*3 + kx];
#pragma unroll
                        for (int p = 0; p < 4; p++) fma2(acc[co][p], w, vv[p]);
                    }
                }
            }
        }
        __syncthreads();
    }
#pragma unroll
    for (int co = 0; co < C_CO; co++) {
        int gco = cb + co;
        if (gco >= Cout) break;
        float bv = bias ? bias[gco] : 0.f;
        ull bv2 = pk2(bv, bv);
        float* op = out + ((size_t)(b*CoutS + coutOff + gco))*HWSZ + (y0g + ty)*WW + x0g + xo;
#pragma unroll
        for (int p = 0; p < 4; p++) {
            ull r = add2(acc[co][p], bv2);
            *(ull*)(op + 2*p) = r;
        }
    }
}

// ---------------- instance norm + leaky relu (in place, float4) ----------
__global__ void instnorm_lrelu_kernel(float* __restrict__ x, const float* __restrict__ gamma,
                                      const float* __restrict__ beta, int C, int rnd)
{
    const int bc = blockIdx.x;
    float4* p = (float4*)(x + (size_t)bc*HWSZ);
    const int N4 = HWSZ/4;
    const int tid = threadIdx.x;
    float s = 0.f, s2 = 0.f;
    for (int i = tid; i < N4; i += 256) {
        float4 v = p[i];
        s  += v.x + v.y + v.z + v.w;
        s2 += v.x*v.x + v.y*v.y + v.z*v.z + v.w*v.w;
    }
    __shared__ float rs[256], rq[256];
    rs[tid] = s; rq[tid] = s2; __syncthreads();
    for (int off = 128; off > 0; off >>= 1) {
        if (tid < off) { rs[tid] += rs[tid+off]; rq[tid] += rq[tid+off]; }
        __syncthreads();
    }
    const float mu  = rs[0]*(1.f/HWSZ);
    const float var = rq[0]*(1.f/HWSZ) - mu*mu;
    const float inv = rsqrtf(var + 1e-5f);
    const int c = bc % C;
    const float ga = gamma[c]*inv, be = beta[c];
    for (int i = tid; i < N4; i += 256) {
        float4 v = p[i];
        v.x = (v.x-mu)*ga + be; v.x = (v.x >= 0.f) ? v.x : 0.2f*v.x;
        v.y = (v.y-mu)*ga + be; v.y = (v.y >= 0.f) ? v.y : 0.2f*v.y;
        v.z = (v.z-mu)*ga + be; v.z = (v.z >= 0.f) ? v.z : 0.2f*v.z;
        v.w = (v.w-mu)*ga + be; v.w = (v.w >= 0.f) ? v.w : 0.2f*v.w;
        if (rnd) {
            v.x = rndtf(v.x); v.y = rndtf(v.y); v.z = rndtf(v.z); v.w = rndtf(v.w);
        }
        p[i] = v;
    }
}

// ---------------- fused separable gaussian blur (replicate pad) ----------
__global__ void blur_fused_kernel(const float* __restrict__ in, int CinS, int cinOff,
                                  float* __restrict__ out, int C)
{
    __shared__ float sraw[22*72];
    __shared__ float sh[22*64];
    const int bx = blockIdx.x, by = blockIdx.y, bc = blockIdx.z;
    const int b = bc / C, c = bc % C;
    const int tid = threadIdx.x;
    const float* ip = in + ((size_t)(b*CinS + cinOff + c))*HWSZ;

    for (int idx = tid; idx < 22*70; idx += 256) {
        int r = idx / 70, cc = idx - r*70;
        int gy = min(max(by*16 + r - 3, 0), HH-1);
        int gx = min(max(bx*64 + cc - 3, 0), WW-1);
        sraw[r*72 + cc] = ip[gy*WW + gx];
    }
    __syncthreads();
    for (int idx = tid; idx < 22*64; idx += 256) {
        int r = idx >> 6, x = idx & 63;
        const float* rp = &sraw[r*72 + x];
        float s = 0.f;
#pragma unroll
        for (int t = 0; t < 7; t++) s += GK[t]*rp[t];
        sh[r*64 + x] = s;
    }
    __syncthreads();
    for (int k = tid; k < 16*64; k += 256) {
        int r = k >> 6, x = k & 63;
        float s = 0.f;
#pragma unroll
        for (int t = 0; t < 7; t++) s += GK[t]*sh[(r+t)*64 + x];
        out[(size_t)bc*HWSZ + (size_t)(by*16 + r)*WW + bx*64 + x] = s;
    }
}

// ---------------- local correlation: 2 px/thread, window reuse, FFMA2 ------
#define CW 40
__global__ void corr_kernel(const float* __restrict__ f1s, const float* __restrict__ f2base,
                            float* __restrict__ out, float* __restrict__ lcsum)
{
    __shared__ float s1[22*CW];
    __shared__ float red[256];
    const int bx = blockIdx.x, by = blockIdx.y, b = blockIdx.z;
    const int tid = threadIdx.x;
    const int ty = tid >> 4, tx = tid & 15;
    const int gy = by*16 + ty, gx = bx*32 + tx*2;

    ull acc2[49];
#pragma unroll
    for (int k = 0; k < 49; k++) acc2[k] = 0ull;

    for (int c = 0; c < 64; c++) {
        const float* p1 = f1s    + ((size_t)(b*64  + c))*HWSZ;
        const float* p2 = f2base + ((size_t)(b*128 + 64 + c))*HWSZ;
        for (int idx = tid; idx < 22*CW; idx += 256) {
            int r = idx / CW, cc = idx - r*CW;
            int yy = by*16 + r - 3, xx = bx*32 + cc - 3;
            s1[idx] = (yy >= 0 && yy < HH && xx >= 0 && xx < WW) ? p1[yy*WW+xx] : 0.f;
        }
        __syncthreads();
        const float v2a = p2[gy*WW + gx];
        const float v2b = p2[gy*WW + gx + 1];
#pragma unroll
        for (int i = 0; i < 7; i++) {
            const float* row = &s1[(ty+i)*CW + tx*2];
            float r[8];
#pragma unroll
            for (int q = 0; q < 8; q++) r[q] = row[q];
#pragma unroll
            for (int j = 0; j < 7; j++) {
                float d0 = v2a - r[j];
                float d1 = v2b - r[j+1];
                ull d = pk2(d0, d1);
                fma2(acc2[i*7+j], d, d);
            }
        }
        __syncthreads();
    }
    float tsum = 0.f;
#pragma unroll
    for (int k = 0; k < 49; k++) {
        float lo, hi; up2(lo, hi, acc2[k]);
        float2 lc; lc.x = lo*(1.f/64.f); lc.y = hi*(1.f/64.f);
        *(float2*)&out[((size_t)(b*128 + 64 + k))*HWSZ + gy*WW + gx] = lc;
        tsum += lc.x + lc.y;
    }
    red[tid] = tsum; __syncthreads();
    for (int off = 128; off > 0; off >>= 1) {
        if (tid < off) red[tid] += red[tid+off];
        __syncthreads();
    }
    if (tid == 0) atomicAdd(&lcsum[b], red[0]);
}

__global__ void zero_lcsum_kernel(float* lcsum)
{
    if (threadIdx.x < BB) lcsum[threadIdx.x] = 0.f;
}

// ---------------- host side ----------------
template<int COUT, int CIN, int DIL, int WMODE, int FCVT>
static void launch_mma(const float* in, int CinS, int cinOff,
                       const float* wp, const float* bias,
                       float* out, int CoutS, int coutOff, float* out2,
                       const float* lcs)
{
    constexpr int NR = 2 + 2*DIL;
    const int smem = (NR*KC*PWD + 9*2*(COUT/16)*128)*4;
    cudaFuncSetAttribute(conv_mma<COUT,CIN,DIL,WMODE,FCVT>,
                         cudaFuncAttributeMaxDynamicSharedMemorySize, smem);
    conv_mma<COUT,CIN,DIL,WMODE,FCVT><<<dim3(2, HH/2, BB), 512, smem>>>(
        in, CinS, cinOff, wp, bias, out, CoutS, coutOff, out2, lcs);
}

extern "C" void kernel_launch(void* const* d_in, const int* in_sizes, int n_in,
                              void* d_out, int out_size)
{
    const float* feat1  = (const float*)d_in[0];
    const float* feat2  = (const float*)d_in[1];
    const float* pre_w  = (const float*)d_in[2];
    const float* pre_b  = (const float*)d_in[3];
    const float* fc1_w  = (const float*)d_in[4];
    const float* fc1_g  = (const float*)d_in[5];
    const float* fc1_be = (const float*)d_in[6];
    const float* fc2_w  = (const float*)d_in[7];
    const float* fc2_b  = (const float*)d_in[8];
    const float* e1_w   = (const float*)d_in[9];
    const float* e1_g   = (const float*)d_in[10];
    const float* e1_be  = (const float*)d_in[11];
    const float* e2_w   = (const float*)d_in[12];
    const float* e2_g   = (const float*)d_in[13];
    const float* e2_be  = (const float*)d_in[14];
    const float* e3_w   = (const float*)d_in[15];
    const float* e3_g   = (const float*)d_in[16];
    const float* e3_be  = (const float*)d_in[17];
    const float* head_w = (const float*)d_in[18];
    const float* head_b = (const float*)d_in[19];
    float* out = (float*)d_out;

    float *cat_, *cattf, *x128, *corr_, *f1s, *x64, *x32, *x16, *head_, *lcsum, *wpb;
    cudaGetSymbolAddress((void**)&cat_,  g_cat);
    cudaGetSymbolAddress((void**)&cattf, g_cattf);
    cudaGetSymbolAddress((void**)&x128,  g_x128);
    cudaGetSymbolAddress((void**)&corr_, g_corr);
    cudaGetSymbolAddress((void**)&f1s,   g_f1s);
    cudaGetSymbolAddress((void**)&x64,   g_x64);
    cudaGetSymbolAddress((void**)&x32,   g_x32);
    cudaGetSymbolAddress((void**)&x16,   g_x16);
    cudaGetSymbolAddress((void**)&head_, g_head);
    cudaGetSymbolAddress((void**)&lcsum, g_lcsum);
    cudaGetSymbolAddress((void**)&wpb,   g_wp);

    float* wp_pre = wpb;
    float* wp_fc1 = wpb + 36864;
    float* wp_fc2 = wpb + 184320;
    float* wp_e1  = wpb + 258048;
    float* wp_e2  = wpb + 331776;
    float* wp_e3  = wpb + 350208;

    // weight prep (fragment-swizzled, tf32, ci-padded)
    prep_all_kernel<<<(354816 + 255)/256, 256>>>(pre_w, fc1_w, fc2_w, e1_w, e2_w, e3_w, wpb);

    // preprocessor (cvt fill from raw feats) -> cat (raw) + cattf (rounded)
    launch_mma<64,64,1,2,1>(feat1, 64, 0, wp_pre, pre_b, cat_, 128, 0, cattf, nullptr);
    launch_mma<64,64,1,2,1>(feat2, 64, 0, wp_pre, pre_b, cat_, 128, 64, cattf, nullptr);

    // featcompressor layer1 + IN(+round)
    launch_mma<128,128,1,0,0>(cattf, 128, 0, wp_fc1, nullptr, x128, 128, 0, nullptr, nullptr);
    instnorm_lrelu_kernel<<<BB*128, 256>>>(x128, fc1_g, fc1_be, 128, 1);

    // featcompressor layer2 -> corr channels 0..63 (rounded)
    launch_mma<64,128,1,1,0>(x128, 128, 0, wp_fc2, fc2_b, corr_, 128, 0, nullptr, nullptr);

    // fused gaussian blur of f1 (raw cat)
    blur_fused_kernel<<<dim3(4, 16, BB*64), 256>>>(cat_, 128, 0, f1s, 64);

    // local correlation -> corr channels 64..112 (raw; normalized at e1 fill)
    zero_lcsum_kernel<<<1, 32>>>(lcsum);
    corr_kernel<<<dim3(WW/32, HH/16, BB), 256>>>(f1s, cat_, corr_, lcsum);

    // estimator stack (e1 fill scales+rounds lc channels via lcsum)
    launch_mma<64,128,1,0,2>(corr_, 128, 0, wp_e1, nullptr, x64, 64, 0, nullptr, lcsum);
    instnorm_lrelu_kernel<<<BB*64, 256>>>(x64, e1_g, e1_be, 64, 1);

    launch_mma<32,64,2,0,0>(x64, 64, 0, wp_e2, nullptr, x32, 32, 0, nullptr, nullptr);
    instnorm_lrelu_kernel<<<BB*32, 256>>>(x32, e2_g, e2_be, 32, 1);

    launch_mma<16,32,4,0,0>(x32, 32, 0, wp_e3, nullptr, x16, 16, 0, nullptr, nullptr);
    instnorm_lrelu_kernel<<<BB*16, 256>>>(x16, e3_g, e3_be, 16, 0);   // head needs raw

    // flow head (tiny, FFMA2 direct conv)
    {
        dim3 grid(1, (WW/C_TW)*(HH/C_TH), BB);
        conv3x3_kernel<1><<<grid, C_NT>>>(x16, 16, 16, 0, head_w, head_b, head_, 2, 2, 0);
    }

    // final fused blur -> output
    blur_fused_kernel<<<dim3(4, 16, BB*2), 256>>>(head_, 2, 0, out, 2);
}